// round 11
// baseline (speedup 1.0000x reference)
#include <cuda_runtime.h>
#include <cuda_fp16.h>
#include <math.h>

#define NB      8
#define NODE    1024
#define TT      12
#define DIN     16
#define HID     32
#define HEADS   3
#define CD      384
#define NNODES  8192
#define NE      65536
#define PLEN    6
#define KDIM    1152        // HEADS*CD

// ---------------- scratch (static device memory) ----------------
__device__ __half   g_gatin16[NNODES*CD];    // GRU output, fp16 (agg gather source)
__device__ float    g_vsrc  [CD*HEADS];
__device__ float    g_vdst  [CD*HEADS];
__device__ float    g_kedge [HEADS];
__device__ __half   g_B16   [CD*KDIM];      // B[n][k] row-major fp16 (permuted Wgat)
__device__ float    g_asrc  [NNODES*HEADS];
__device__ float    g_adst  [NNODES*HEADS];
__device__ int      g_count [NNODES];        // static-zero; re-zeroed by k_scan each run
__device__ int      g_off   [NNODES+1];
__device__ int      g_cur   [NNODES];
__device__ float2   g_ew2   [NE];            // (src, edge_attr) sorted by dst
__device__ __half   g_Z16   [NNODES*KDIM];
__device__ float    g_gatout[NNODES*CD];
__device__ unsigned g_pooled[NB*CD] = {};    // reset by k_cls each run (init value below)

__device__ __forceinline__ unsigned fenc(float f){
    unsigned u = __float_as_uint(f);
    return (u & 0x80000000u) ? ~u : (u | 0x80000000u);
}
__device__ __forceinline__ float fdec(unsigned u){
    unsigned v = (u & 0x80000000u) ? (u & 0x7fffffffu) : ~u;
    return __uint_as_float(v);
}
__device__ __forceinline__ unsigned smem_u32(const void* p){
    unsigned a;
    asm("{ .reg .u64 t; cvta.to.shared.u64 t, %1; cvt.u32.u64 %0, t; }" : "=r"(a) : "l"(p));
    return a;
}

// ---------------- mma.sync helpers ----------------
#define LDSM4(r, a)                                                                 \
    asm volatile("ldmatrix.sync.aligned.m8n8.x4.shared.b16 {%0,%1,%2,%3}, [%4];"    \
        : "=r"((r)[0]), "=r"((r)[1]), "=r"((r)[2]), "=r"((r)[3]) : "r"(a))

#define MMAF16(d, a, b)                                                             \
    asm volatile("mma.sync.aligned.m16n8k16.row.col.f32.f16.f16.f32 "               \
        "{%0,%1,%2,%3}, {%4,%5,%6,%7}, {%8,%9}, {%0,%1,%2,%3};"                     \
        : "+f"((d)[0]), "+f"((d)[1]), "+f"((d)[2]), "+f"((d)[3])                    \
        : "r"((a)[0]), "r"((a)[1]), "r"((a)[2]), "r"((a)[3]),                       \
          "r"((b)[0]), "r"((b)[1]))

// ---------------- attention projection vectors + kedge (no deps; runs from root) -------
// grid (13, 3): x<12 -> vsrc/vdst chunk; x==12 -> kedge[h]
__global__ void __launch_bounds__(256) k_vecs_r(const float* __restrict__ Wgat,
                                                const float* __restrict__ att_src,
                                                const float* __restrict__ att_dst,
                                                const float* __restrict__ Wedge,
                                                const float* __restrict__ att_edge){
    int h = blockIdx.y;
    if (blockIdx.x == 12){
        if (threadIdx.x < 32){
            int lane = threadIdx.x;
            float s = 0.f;
            for (int c = lane; c < CD; c += 32) s += Wedge[h*CD + c]*att_edge[h*CD + c];
            #pragma unroll
            for (int o = 16; o; o >>= 1) s += __shfl_xor_sync(0xffffffffu, s, o);
            if (lane == 0) g_kedge[h] = s;
        }
        return;
    }
    __shared__ float ss[8][32], sd[8][32];
    int f0 = blockIdx.x*32;
    int lane = threadIdx.x & 31, cp = threadIdx.x >> 5;
    float as_ = 0.f, ad_ = 0.f;
    for (int c = cp; c < CD; c += 8){
        float wv = Wgat[((size_t)(h*CD + c))*CD + f0 + lane];
        as_ += wv * att_src[h*CD + c];
        ad_ += wv * att_dst[h*CD + c];
    }
    ss[cp][lane] = as_; sd[cp][lane] = ad_;
    __syncthreads();
    if (cp == 0){
        float s = 0.f, d = 0.f;
        #pragma unroll
        for (int i = 0; i < 8; i++){ s += ss[i][lane]; d += sd[i][lane]; }
        g_vsrc[(f0 + lane)*3 + h] = s;
        g_vdst[(f0 + lane)*3 + h] = d;
    }
}

// ---------------- B fp16 convert (permuted: B[c][k] = Wgat[(h*384+c)*384+f]) ------------
__global__ void k_b16(const float* __restrict__ Wgat){
    int idx = blockIdx.x*blockDim.x + threadIdx.x;
    if (idx >= CD*KDIM) return;
    int c = idx / KDIM, k = idx % KDIM;
    int h = k / CD, f = k % CD;
    g_B16[idx] = __float2half(Wgat[((size_t)(h*CD + c))*CD + f]);
}

// ---------------- fused GRU + attention projections; fp16 output ----------------
__global__ void __launch_bounds__(128) k_gru2(const float* __restrict__ x,
                                              const float* __restrict__ Wih,
                                              const float* __restrict__ Whh,
                                              const float* __restrict__ bih,
                                              const float* __restrict__ bhh){
    int tid = threadIdx.x, lane = tid & 31, w = tid >> 5;
    int wg = blockIdx.x*4 + w;           // 0..4095, 2 nodes each
    float wir[16], wiz[16], win[16];
    float whr[32], whz[32], whn[32];
    #pragma unroll
    for (int d = 0; d < 16; d++){
        wir[d] = Wih[(lane)*16 + d];
        wiz[d] = Wih[(32 + lane)*16 + d];
        win[d] = Wih[(64 + lane)*16 + d];
    }
    #pragma unroll
    for (int k = 0; k < 32; k++){
        whr[k] = Whh[(lane)*32 + k];
        whz[k] = Whh[(32 + lane)*32 + k];
        whn[k] = Whh[(64 + lane)*32 + k];
    }
    float br = bih[lane] + bhh[lane];
    float bz = bih[32+lane] + bhh[32+lane];
    float bni = bih[64+lane];
    float bnh = bhh[64+lane];

    for (int ni = 0; ni < 2; ni++){
        int n = wg*2 + ni;
        float h = 0.f;
        float s0=0,s1=0,s2=0,d0=0,d1=0,d2=0;
        const float* xrow = x + (size_t)n*TT*DIN;
        __half* outp = g_gatin16 + (size_t)n*CD;
        for (int t = 0; t < TT; t++){
            float xv = (lane < DIN) ? xrow[t*DIN + lane] : 0.f;
            float gr = br, gz = bz, gn = bni;
            #pragma unroll
            for (int d = 0; d < DIN; d++){
                float xd = __shfl_sync(0xffffffffu, xv, d);
                gr += wir[d]*xd; gz += wiz[d]*xd; gn += win[d]*xd;
            }
            float ar = 0.f, az = 0.f, an = 0.f;
            #pragma unroll
            for (int k = 0; k < 32; k++){
                float hk = __shfl_sync(0xffffffffu, h, k);
                ar += whr[k]*hk; az += whz[k]*hk; an += whn[k]*hk;
            }
            float r  = 1.f/(1.f + __expf(-(gr + ar)));
            float z  = 1.f/(1.f + __expf(-(gz + az)));
            float nn = tanhf(gn + r*(an + bnh));
            h = (1.f - z)*nn + z*h;
            outp[t*32 + lane] = __float2half(h);
            int f = t*32 + lane;
            s0 += h*g_vsrc[f*3+0]; s1 += h*g_vsrc[f*3+1]; s2 += h*g_vsrc[f*3+2];
            d0 += h*g_vdst[f*3+0]; d1 += h*g_vdst[f*3+1]; d2 += h*g_vdst[f*3+2];
        }
        #pragma unroll
        for (int o = 16; o; o >>= 1){
            s0 += __shfl_xor_sync(0xffffffffu, s0, o);
            s1 += __shfl_xor_sync(0xffffffffu, s1, o);
            s2 += __shfl_xor_sync(0xffffffffu, s2, o);
            d0 += __shfl_xor_sync(0xffffffffu, d0, o);
            d1 += __shfl_xor_sync(0xffffffffu, d1, o);
            d2 += __shfl_xor_sync(0xffffffffu, d2, o);
        }
        if (lane == 0){
            g_asrc[n*3+0]=s0; g_asrc[n*3+1]=s1; g_asrc[n*3+2]=s2;
            g_adst[n*3+0]=d0; g_adst[n*3+1]=d1; g_adst[n*3+2]=d2;
        }
    }
}

// ---------------- edge pipeline (runs from graph root on s2) ----------------
__global__ void k_count(const int* __restrict__ ei){
    int i = blockIdx.x*blockDim.x + threadIdx.x;
    int4 d = ((const int4*)(ei + NE))[i];
    atomicAdd(&g_count[d.x], 1);
    atomicAdd(&g_count[d.y], 1);
    atomicAdd(&g_count[d.z], 1);
    atomicAdd(&g_count[d.w], 1);
}

__global__ void k_scan(){
    __shared__ int sh[1024];
    int t = threadIdx.x;
    int loc[8];
    int base = t*8;
    int s = 0;
    #pragma unroll
    for (int i = 0; i < 8; i++){ loc[i] = s; s += g_count[base+i]; }
    sh[t] = s; __syncthreads();
    for (int off = 1; off < 1024; off <<= 1){
        int v = (t >= off) ? sh[t-off] : 0;
        __syncthreads();
        sh[t] += v;
        __syncthreads();
    }
    int excl = (t == 0) ? 0 : sh[t-1];
    #pragma unroll
    for (int i = 0; i < 8; i++){
        int o = excl + loc[i];
        g_off[base+i] = o; g_cur[base+i] = o;
        g_count[base+i] = 0;               // restore for next graph replay
    }
    if (t == 1023) g_off[NNODES] = excl + s;
}

__global__ void k_scat(const int* __restrict__ ei, const float* __restrict__ ea){
    int e = blockIdx.x*blockDim.x + threadIdx.x;
    if (e >= NE) return;
    int d = ei[NE + e];
    int pos = atomicAdd(&g_cur[d], 1);
    g_ew2[pos] = make_float2(__int_as_float(ei[e]), ea[e]);
}

// ---------------- aggregation: fused logit+exp+softmax+gather -> fp16 Z ----------------
// block = node (192 threads); thread t owns half2 channel pair 2t,2t+1 (per head).
__global__ void __launch_bounds__(192) k_agg3(int nbase){
    __shared__ float sw[32*3];
    __shared__ int   ssrc[32];
    int n = blockIdx.x + nbase;
    int tid = threadIdx.x;
    int s0 = g_off[n], s1 = g_off[n+1];
    float ad0 = g_adst[n*3+0], ad1 = g_adst[n*3+1], ad2 = g_adst[n*3+2];
    float ke0 = g_kedge[0], ke1 = g_kedge[1], ke2 = g_kedge[2];
    float a0x=0,a0y=0,a1x=0,a1y=0,a2x=0,a2y=0;
    float dn0=0.f, dn1=0.f, dn2=0.f;
    const __half2* gi = (const __half2*)g_gatin16;

    for (int c = s0; c < s1; c += 32){
        int m = s1 - c; if (m > 32) m = 32;
        if (tid < m*3){
            int j = tid / 3, hh = tid - 3*j;
            float2 q = g_ew2[c + j];
            int src = __float_as_int(q.x);
            float ad = (hh == 0) ? ad0 : ((hh == 1) ? ad1 : ad2);
            float ke = (hh == 0) ? ke0 : ((hh == 1) ? ke1 : ke2);
            float l = g_asrc[src*3 + hh] + ad + q.y*ke;
            l = (l > 0.f) ? l : 0.2f*l;          // leaky_relu 0.2
            sw[j*3 + hh] = __expf(l);            // logits O(1): no max-shift
            if (hh == 0) ssrc[j] = src;
        }
        __syncthreads();
        for (int j = 0; j < m; j++){
            int src = ssrc[j];
            float c0 = sw[j*3+0], c1 = sw[j*3+1], c2 = sw[j*3+2];
            float2 v = __half22float2(gi[(size_t)src*(CD/2) + tid]);
            a0x += c0*v.x; a0y += c0*v.y;
            a1x += c1*v.x; a1y += c1*v.y;
            a2x += c2*v.x; a2y += c2*v.y;
            dn0 += c0; dn1 += c1; dn2 += c2;
        }
        __syncthreads();
    }
    float inv0 = (1.f/3.f)/(dn0 + 1e-16f);
    float inv1 = (1.f/3.f)/(dn1 + 1e-16f);
    float inv2 = (1.f/3.f)/(dn2 + 1e-16f);
    __half2* z = (__half2*)g_Z16;
    size_t zb = (size_t)n*(KDIM/2);
    z[zb + 0*(CD/2) + tid] = __floats2half2_rn(a0x*inv0, a0y*inv0);
    z[zb + 1*(CD/2) + tid] = __floats2half2_rn(a1x*inv1, a1y*inv1);
    z[zb + 2*(CD/2) + tid] = __floats2half2_rn(a2x*inv2, a2y*inv2);
}

// ---------------- GEMM via mma.sync fp16 (M-tile range param) ----------------
#define ROWP    72
#define OFF_B   18432u                // 128*72*2
#define BUF_SZ  46080u                // + 192*72*2
#define GSM_TOT (2u*BUF_SZ)           // 90 KB

__device__ __forceinline__ void gfill(unsigned sb, int tid, int buf, int kc, int m0, int n0){
    unsigned base = sb + (unsigned)buf*BUF_SZ;
    for (int u = tid; u < 2560; u += 384){
        const __half* src;
        unsigned off;
        if (u < 1024){
            int r = u >> 3, s = u & 7;
            src = g_Z16 + (size_t)(m0 + r)*KDIM + kc*64 + s*8;
            off = (unsigned)(r*ROWP + s*8)*2u;
        } else {
            int v = u - 1024;
            int r = v >> 3, s = v & 7;
            src = g_B16 + (size_t)(n0 + r)*KDIM + kc*64 + s*8;
            off = OFF_B + (unsigned)(r*ROWP + s*8)*2u;
        }
        asm volatile("cp.async.ca.shared.global [%0], [%1], 16;"
                     :: "r"(base + off), "l"(src) : "memory");
    }
    asm volatile("cp.async.commit_group;" ::: "memory");
}

__global__ void __launch_bounds__(384, 1) k_gemm_mma(const float* __restrict__ bias, int ybase){
    extern __shared__ char sm[];
    unsigned sb = smem_u32(sm);
    int tid = threadIdx.x, lane = tid & 31, w = tid >> 5;
    int m0 = (blockIdx.y + ybase)*128, n0 = blockIdx.x*192;
    int wm = (w & 3)*32, wn = (w >> 2)*64;

    float acc[2][8][4];
    #pragma unroll
    for (int i = 0; i < 2; i++)
        #pragma unroll
        for (int j = 0; j < 8; j++)
            #pragma unroll
            for (int q = 0; q < 4; q++) acc[i][j][q] = 0.f;

    gfill(sb, tid, 0, 0, m0, n0);
    for (int kc = 0; kc < 18; kc++){
        if (kc + 1 < 18){
            gfill(sb, tid, (kc+1)&1, kc+1, m0, n0);
            asm volatile("cp.async.wait_group 1;" ::: "memory");
        } else {
            asm volatile("cp.async.wait_group 0;" ::: "memory");
        }
        __syncthreads();
        unsigned base = sb + (unsigned)(kc&1)*BUF_SZ;
        #pragma unroll
        for (int ks = 0; ks < 4; ks++){
            int kk = ks*16;
            unsigned aa[2][4];
            #pragma unroll
            for (int mi = 0; mi < 2; mi++){
                int row = wm + mi*16 + (lane & 15);
                int col = kk + 8*(lane >> 4);
                LDSM4(aa[mi], base + (unsigned)(row*ROWP + col)*2u);
            }
            unsigned bb[4][4];
            #pragma unroll
            for (int p = 0; p < 4; p++){
                int row = wn + p*16 + (lane & 7) + 8*(lane >> 4);
                int col = kk + 8*((lane >> 3) & 1);
                LDSM4(bb[p], base + OFF_B + (unsigned)(row*ROWP + col)*2u);
            }
            #pragma unroll
            for (int mi = 0; mi < 2; mi++)
                #pragma unroll
                for (int nj = 0; nj < 8; nj++)
                    MMAF16(acc[mi][nj], aa[mi], (&bb[nj>>1][(nj&1)*2]));
        }
        __syncthreads();
    }

    int r0 = lane >> 2, c0 = 2*(lane & 3);
    #pragma unroll
    for (int mi = 0; mi < 2; mi++)
        #pragma unroll
        for (int nj = 0; nj < 8; nj++){
            int row = m0 + wm + mi*16 + r0;
            int col = n0 + wn + nj*8 + c0;
            float b0 = bias[col], b1 = bias[col+1];
            *(float2*)&g_gatout[(size_t)row*CD + col] =
                make_float2(acc[mi][nj][0] + b0, acc[mi][nj][1] + b1);
            *(float2*)&g_gatout[(size_t)(row+8)*CD + col] =
                make_float2(acc[mi][nj][2] + b0, acc[mi][nj][3] + b1);
        }
}

// ---------------- predictor: warp per node ----------------
__global__ void k_pred(const float* __restrict__ Wp1, const float* __restrict__ bp1,
                       const float* __restrict__ Wp3, const float* __restrict__ bp3,
                       float* __restrict__ out){
    int warp = threadIdx.x >> 5, lane = threadIdx.x & 31;
    int n = blockIdx.x*8 + warp;
    const float* row = g_gatout + (size_t)n*CD;
    float w1 = Wp1[lane];
    float b1 = bp1[0];
    float p[TT];
    #pragma unroll
    for (int t = 0; t < TT; t++){
        float s = row[t*HID + lane]*w1;
        #pragma unroll
        for (int o = 16; o; o >>= 1) s += __shfl_xor_sync(0xffffffffu, s, o);
        s += b1;
        p[t] = (s > 0.f) ? s : 0.f;
    }
    if (lane < PLEN){
        float q = bp3[lane];
        #pragma unroll
        for (int t = 0; t < TT; t++) q += p[t]*Wp3[lane*TT + t];
        out[(size_t)n*PLEN + lane] = (q > 0.f) ? q : 0.f;
    }
}

// ---------------- batch max-pool ----------------
__global__ void k_pool(const int* __restrict__ bv){
    int g0 = blockIdx.x*128;
    int c  = threadIdx.x;
    int b  = bv[g0];
    float m = -3.0e38f;
    for (int i = 0; i < 128; i++){
        float v = g_gatout[(size_t)(g0+i)*CD + c];
        m = fmaxf(m, v);
    }
    atomicMax(&g_pooled[b*CD + c], fenc(m));
}

// ---------------- classifier + softmax; resets g_pooled for next replay ----------------
__global__ void k_cls(const float* __restrict__ Wc1, const float* __restrict__ bc1,
                      const float* __restrict__ Wc2, const float* __restrict__ bc2,
                      float* __restrict__ out, int out_size){
    __shared__ float l1[NB][32];
    __shared__ float l2[NB][2];
    int tid = threadIdx.x;
    int b = tid >> 5, i = tid & 31;
    float a = bc1[i];
    for (int c = 0; c < CD; c++) a += fdec(g_pooled[b*CD + c]) * Wc1[i*CD + c];
    l1[b][i] = a;
    __syncthreads();
    // reset pooled for next graph replay (all reads are done)
    unsigned neg = fenc(-3.0e38f);
    for (int q = tid; q < NB*CD; q += 256) g_pooled[q] = neg;
    if (tid < NB*2){
        int bb = tid >> 1, j = tid & 1;
        float v = bc2[j];
        for (int k = 0; k < 32; k++) v += l1[bb][k]*Wc2[j*32 + k];
        l2[bb][j] = v;
    }
    __syncthreads();
    if (tid < NB*2){
        int bb = tid >> 1, j = tid & 1;
        float m = fmaxf(l2[bb][0], l2[bb][1]);
        float e0 = __expf(l2[bb][0] - m), e1 = __expf(l2[bb][1] - m);
        out[out_size - NB*2 + bb*2 + j] = ((j == 0) ? e0 : e1) / (e0 + e1);
    }
}

// ---------------- launch: init-free DAG ----------------
extern "C" void kernel_launch(void* const* d_in, const int* in_sizes, int n_in,
                              void* d_out, int out_size){
    const float* x   = (const float*)d_in[0];
    const int*   ei  = (const int*)  d_in[1];
    const float* ea  = (const float*)d_in[2];
    const int*   bv  = (const int*)  d_in[3];
    int wb = (n_in >= 23 && in_sizes[4] == 1) ? 5 : 4;
    const float* Wih      = (const float*)d_in[wb+0];
    const float* Whh      = (const float*)d_in[wb+1];
    const float* bih      = (const float*)d_in[wb+2];
    const float* bhh      = (const float*)d_in[wb+3];
    const float* Wgat     = (const float*)d_in[wb+4];
    const float* att_src  = (const float*)d_in[wb+5];
    const float* att_dst  = (const float*)d_in[wb+6];
    const float* Wedge    = (const float*)d_in[wb+7];
    const float* att_edge = (const float*)d_in[wb+8];
    const float* gat_bias = (const float*)d_in[wb+9];
    const float* Wp1      = (const float*)d_in[wb+10];
    const float* bp1      = (const float*)d_in[wb+11];
    const float* Wp3      = (const float*)d_in[wb+12];
    const float* bp3      = (const float*)d_in[wb+13];
    const float* Wc1      = (const float*)d_in[wb+14];
    const float* bc1      = (const float*)d_in[wb+15];
    const float* Wc2      = (const float*)d_in[wb+16];
    const float* bc2      = (const float*)d_in[wb+17];
    float* out = (float*)d_out;

    static cudaStream_t s2 = 0, s3 = 0;
    static cudaEvent_t evRoot = 0, evVecs = 0, evScat = 0, evB16 = 0;
    static cudaEvent_t evAgg0 = 0, evGemm0 = 0, evGemmAll = 0, evCls = 0;
    if (!s2){
        cudaStreamCreateWithFlags(&s2, cudaStreamNonBlocking);
        cudaStreamCreateWithFlags(&s3, cudaStreamNonBlocking);
        cudaEventCreateWithFlags(&evRoot,    cudaEventDisableTiming);
        cudaEventCreateWithFlags(&evVecs,    cudaEventDisableTiming);
        cudaEventCreateWithFlags(&evScat,    cudaEventDisableTiming);
        cudaEventCreateWithFlags(&evB16,     cudaEventDisableTiming);
        cudaEventCreateWithFlags(&evAgg0,    cudaEventDisableTiming);
        cudaEventCreateWithFlags(&evGemm0,   cudaEventDisableTiming);
        cudaEventCreateWithFlags(&evGemmAll, cudaEventDisableTiming);
        cudaEventCreateWithFlags(&evCls,     cudaEventDisableTiming);
        cudaFuncSetAttribute(k_gemm_mma, cudaFuncAttributeMaxDynamicSharedMemorySize, GSM_TOT);
    }

    cudaEventRecord(evRoot, 0);

    // s2: full edge sort pipeline — starts at t=0 (count zeroed by prior scan/static init)
    cudaStreamWaitEvent(s2, evRoot, 0);
    k_count<<<NE/1024, 256, 0, s2>>>(ei);
    k_scan <<<1, 1024, 0, s2>>>();
    k_scat <<<NE/256, 256, 0, s2>>>(ei, ea);
    cudaEventRecord(evScat, s2);

    // s3: vecs+kedge (no deps) -> b16 convert
    cudaStreamWaitEvent(s3, evRoot, 0);
    k_vecs_r<<<dim3(13, 3), 256, 0, s3>>>(Wgat, att_src, att_dst, Wedge, att_edge);
    cudaEventRecord(evVecs, s3);
    k_b16   <<<(CD*KDIM + 255)/256, 256, 0, s3>>>(Wgat);
    cudaEventRecord(evB16, s3);

    // main: gru2 (needs vecs), then fused agg (needs scat)
    cudaStreamWaitEvent(0, evVecs, 0);
    k_gru2 <<<1024, 128>>>(x, Wih, Whh, bih, bhh);
    cudaStreamWaitEvent(0, evScat, 0);
    k_agg3 <<<NNODES/2, 192>>>(0);
    cudaEventRecord(evAgg0, 0);
    k_agg3 <<<NNODES/2, 192>>>(NNODES/2);

    // s3: gemm lower half overlapped with agg upper half
    cudaStreamWaitEvent(s3, evAgg0, 0);
    k_gemm_mma<<<dim3(2, 32), 384, GSM_TOT, s3>>>(gat_bias, 0);
    cudaEventRecord(evGemm0, s3);

    // main: gemm upper half (needs b16)
    cudaStreamWaitEvent(0, evB16, 0);
    k_gemm_mma<<<dim3(2, 32), 384, GSM_TOT>>>(gat_bias, 32);
    cudaStreamWaitEvent(0, evGemm0, 0);
    cudaEventRecord(evGemmAll, 0);

    // s2: pool + cls after full gemm
    cudaStreamWaitEvent(s2, evGemmAll, 0);
    k_pool <<<64, 384, 0, s2>>>(bv);
    k_cls  <<<1, 256, 0, s2>>>(Wc1, bc1, Wc2, bc2, out, out_size);
    cudaEventRecord(evCls, s2);

    // main: pred, then join cls
    k_pred <<<1024, 256>>>(Wp1, bp1, Wp3, bp3, out);
    cudaStreamWaitEvent(0, evCls, 0);
}

// round 12
// speedup vs baseline: 1.0666x; 1.0666x over previous
#include <cuda_runtime.h>
#include <cuda_fp16.h>
#include <math.h>

#define NB      8
#define NODE    1024
#define TT      12
#define DIN     16
#define HID     32
#define HEADS   3
#define CD      384
#define NNODES  8192
#define NE      65536
#define PLEN    6
#define KDIM    1152        // HEADS*CD

// ---------------- scratch (static device memory) ----------------
__device__ float    g_gatin [NNODES*CD];
__device__ float    g_vsrc  [CD*HEADS];
__device__ float    g_vdst  [CD*HEADS];
__device__ float    g_kedge [HEADS];
__device__ __half   g_B16   [CD*KDIM];      // B[n][k] row-major fp16 (permuted Wgat)
__device__ float    g_asrc  [NNODES*HEADS];
__device__ float    g_adst  [NNODES*HEADS];
__device__ int      g_count [NNODES];        // static-zero; re-zeroed by k_scan each run
__device__ int      g_off   [NNODES+1];
__device__ int      g_cur   [NNODES];
__device__ float2   g_ew2   [NE];            // (src, edge_attr) sorted by dst
__device__ __half   g_Z16   [NNODES*KDIM];
__device__ float    g_gatout[NNODES*CD];
__device__ unsigned g_pooled[NB*CD] = {};    // encoded-0 is a valid max identity; k_cls resets

__device__ __forceinline__ unsigned fenc(float f){
    unsigned u = __float_as_uint(f);
    return (u & 0x80000000u) ? ~u : (u | 0x80000000u);
}
__device__ __forceinline__ float fdec(unsigned u){
    unsigned v = (u & 0x80000000u) ? (u & 0x7fffffffu) : ~u;
    return __uint_as_float(v);
}
__device__ __forceinline__ unsigned smem_u32(const void* p){
    unsigned a;
    asm("{ .reg .u64 t; cvta.to.shared.u64 t, %1; cvt.u32.u64 %0, t; }" : "=r"(a) : "l"(p));
    return a;
}

// ---------------- mma.sync helpers ----------------
#define LDSM4(r, a)                                                                 \
    asm volatile("ldmatrix.sync.aligned.m8n8.x4.shared.b16 {%0,%1,%2,%3}, [%4];"    \
        : "=r"((r)[0]), "=r"((r)[1]), "=r"((r)[2]), "=r"((r)[3]) : "r"(a))

#define MMAF16(d, a, b)                                                             \
    asm volatile("mma.sync.aligned.m16n8k16.row.col.f32.f16.f16.f32 "               \
        "{%0,%1,%2,%3}, {%4,%5,%6,%7}, {%8,%9}, {%0,%1,%2,%3};"                     \
        : "+f"((d)[0]), "+f"((d)[1]), "+f"((d)[2]), "+f"((d)[3])                    \
        : "r"((a)[0]), "r"((a)[1]), "r"((a)[2]), "r"((a)[3]),                       \
          "r"((b)[0]), "r"((b)[1]))

// ---------------- attention projection vectors + kedge: COALESCED, 3 blocks ----------
// block = head h (768 threads): group g = tid/384 owns c in [g*192,(g+1)*192),
// thread reads Wgat rows coalesced (f = tid%384), smem-reduce the 2 partials.
__global__ void __launch_bounds__(768) k_vecs_f(const float* __restrict__ Wgat,
                                                const float* __restrict__ att_src,
                                                const float* __restrict__ att_dst,
                                                const float* __restrict__ Wedge,
                                                const float* __restrict__ att_edge){
    __shared__ float ps[2][CD], pd[2][CD];
    int h = blockIdx.x;
    int tid = threadIdx.x;
    int g = tid / CD;
    int f = tid - g*CD;
    float vs = 0.f, vd = 0.f;
    #pragma unroll 4
    for (int c = g*192; c < (g+1)*192; c++){
        float wv = Wgat[((size_t)(h*CD + c))*CD + f];
        vs += wv * att_src[h*CD + c];
        vd += wv * att_dst[h*CD + c];
    }
    ps[g][f] = vs; pd[g][f] = vd;
    __syncthreads();
    if (g == 0){
        g_vsrc[f*3 + h] = ps[0][f] + ps[1][f];
        g_vdst[f*3 + h] = pd[0][f] + pd[1][f];
    }
    if (tid < 32){
        float s = 0.f;
        for (int c = tid; c < CD; c += 32) s += Wedge[h*CD + c]*att_edge[h*CD + c];
        #pragma unroll
        for (int o = 16; o; o >>= 1) s += __shfl_xor_sync(0xffffffffu, s, o);
        if (tid == 0) g_kedge[h] = s;
    }
}

// ---------------- B fp16 convert (permuted: B[c][k] = Wgat[(h*384+c)*384+f]) ------------
__global__ void k_b16(const float* __restrict__ Wgat){
    int idx = blockIdx.x*blockDim.x + threadIdx.x;
    if (idx >= CD*KDIM) return;
    int c = idx / KDIM, k = idx % KDIM;
    int h = k / CD, f = k % CD;
    g_B16[idx] = __float2half(Wgat[((size_t)(h*CD + c))*CD + f]);
}

// ---------------- fused GRU + attention projections (round-10 verified config) ---------
__global__ void __launch_bounds__(128) k_gru2(const float* __restrict__ x,
                                              const float* __restrict__ Wih,
                                              const float* __restrict__ Whh,
                                              const float* __restrict__ bih,
                                              const float* __restrict__ bhh){
    int tid = threadIdx.x, lane = tid & 31, w = tid >> 5;
    int wg = blockIdx.x*4 + w;           // 0..2047, 4 nodes each
    float wir[16], wiz[16], win[16];
    float whr[32], whz[32], whn[32];
    #pragma unroll
    for (int d = 0; d < 16; d++){
        wir[d] = Wih[(lane)*16 + d];
        wiz[d] = Wih[(32 + lane)*16 + d];
        win[d] = Wih[(64 + lane)*16 + d];
    }
    #pragma unroll
    for (int k = 0; k < 32; k++){
        whr[k] = Whh[(lane)*32 + k];
        whz[k] = Whh[(32 + lane)*32 + k];
        whn[k] = Whh[(64 + lane)*32 + k];
    }
    float br = bih[lane] + bhh[lane];
    float bz = bih[32+lane] + bhh[32+lane];
    float bni = bih[64+lane];
    float bnh = bhh[64+lane];

    for (int ni = 0; ni < 4; ni++){
        int n = wg*4 + ni;
        float h = 0.f;
        float s0=0,s1=0,s2=0,d0=0,d1=0,d2=0;
        const float* xrow = x + (size_t)n*TT*DIN;
        float* outp = g_gatin + (size_t)n*CD;
        for (int t = 0; t < TT; t++){
            float xv = (lane < DIN) ? xrow[t*DIN + lane] : 0.f;
            float gr = br, gz = bz, gn = bni;
            #pragma unroll
            for (int d = 0; d < DIN; d++){
                float xd = __shfl_sync(0xffffffffu, xv, d);
                gr += wir[d]*xd; gz += wiz[d]*xd; gn += win[d]*xd;
            }
            float ar = 0.f, az = 0.f, an = 0.f;
            #pragma unroll
            for (int k = 0; k < 32; k++){
                float hk = __shfl_sync(0xffffffffu, h, k);
                ar += whr[k]*hk; az += whz[k]*hk; an += whn[k]*hk;
            }
            float r  = 1.f/(1.f + __expf(-(gr + ar)));
            float z  = 1.f/(1.f + __expf(-(gz + az)));
            float nn = tanhf(gn + r*(an + bnh));
            h = (1.f - z)*nn + z*h;
            outp[t*32 + lane] = h;
            int f = t*32 + lane;
            s0 += h*g_vsrc[f*3+0]; s1 += h*g_vsrc[f*3+1]; s2 += h*g_vsrc[f*3+2];
            d0 += h*g_vdst[f*3+0]; d1 += h*g_vdst[f*3+1]; d2 += h*g_vdst[f*3+2];
        }
        #pragma unroll
        for (int o = 16; o; o >>= 1){
            s0 += __shfl_xor_sync(0xffffffffu, s0, o);
            s1 += __shfl_xor_sync(0xffffffffu, s1, o);
            s2 += __shfl_xor_sync(0xffffffffu, s2, o);
            d0 += __shfl_xor_sync(0xffffffffu, d0, o);
            d1 += __shfl_xor_sync(0xffffffffu, d1, o);
            d2 += __shfl_xor_sync(0xffffffffu, d2, o);
        }
        if (lane == 0){
            g_asrc[n*3+0]=s0; g_asrc[n*3+1]=s1; g_asrc[n*3+2]=s2;
            g_adst[n*3+0]=d0; g_adst[n*3+1]=d1; g_adst[n*3+2]=d2;
        }
    }
}

// ---------------- edge pipeline (runs from graph root on s2) ----------------
__global__ void k_count(const int* __restrict__ ei){
    int i = blockIdx.x*blockDim.x + threadIdx.x;
    int4 d = ((const int4*)(ei + NE))[i];
    atomicAdd(&g_count[d.x], 1);
    atomicAdd(&g_count[d.y], 1);
    atomicAdd(&g_count[d.z], 1);
    atomicAdd(&g_count[d.w], 1);
}

__global__ void k_scan(){
    __shared__ int sh[1024];
    int t = threadIdx.x;
    int loc[8];
    int base = t*8;
    int s = 0;
    #pragma unroll
    for (int i = 0; i < 8; i++){ loc[i] = s; s += g_count[base+i]; }
    sh[t] = s; __syncthreads();
    for (int off = 1; off < 1024; off <<= 1){
        int v = (t >= off) ? sh[t-off] : 0;
        __syncthreads();
        sh[t] += v;
        __syncthreads();
    }
    int excl = (t == 0) ? 0 : sh[t-1];
    #pragma unroll
    for (int i = 0; i < 8; i++){
        int o = excl + loc[i];
        g_off[base+i] = o; g_cur[base+i] = o;
        g_count[base+i] = 0;               // restore for next graph replay
    }
    if (t == 1023) g_off[NNODES] = excl + s;
}

__global__ void k_scat(const int* __restrict__ ei, const float* __restrict__ ea){
    int e = blockIdx.x*blockDim.x + threadIdx.x;
    if (e >= NE) return;
    int d = ei[NE + e];
    int pos = atomicAdd(&g_cur[d], 1);
    g_ew2[pos] = make_float2(__int_as_float(ei[e]), ea[e]);
}

// ---------------- aggregation: fused logit+exp+softmax+gather -> fp16 Z ----------------
// block = node (128 threads); thread t owns channels t, t+128, t+256. (round-10 verified)
__global__ void __launch_bounds__(128) k_agg3(int nbase){
    __shared__ float sw[32*3];
    __shared__ int   ssrc[32];
    int n = blockIdx.x + nbase;
    int tid = threadIdx.x;
    int s0 = g_off[n], s1 = g_off[n+1];
    float ad0 = g_adst[n*3+0], ad1 = g_adst[n*3+1], ad2 = g_adst[n*3+2];
    float ke0 = g_kedge[0], ke1 = g_kedge[1], ke2 = g_kedge[2];
    float a[3][3] = {};
    float dn0=0.f, dn1=0.f, dn2=0.f;

    for (int c = s0; c < s1; c += 32){
        int m = s1 - c; if (m > 32) m = 32;
        if (tid < m*3){
            int j = tid / 3, hh = tid - 3*j;
            float2 q = g_ew2[c + j];
            int src = __float_as_int(q.x);
            float ad = (hh == 0) ? ad0 : ((hh == 1) ? ad1 : ad2);
            float ke = (hh == 0) ? ke0 : ((hh == 1) ? ke1 : ke2);
            float l = g_asrc[src*3 + hh] + ad + q.y*ke;
            l = (l > 0.f) ? l : 0.2f*l;          // leaky_relu 0.2
            sw[j*3 + hh] = __expf(l);            // logits O(1): no max-shift
            if (hh == 0) ssrc[j] = src;
        }
        __syncthreads();
        for (int j = 0; j < m; j++){
            int src = ssrc[j];
            float c0 = sw[j*3+0], c1 = sw[j*3+1], c2 = sw[j*3+2];
            const float* xr = g_gatin + (size_t)src*CD;
            float v0 = xr[tid], v1 = xr[tid+128], v2 = xr[tid+256];
            a[0][0] += c0*v0; a[0][1] += c0*v1; a[0][2] += c0*v2;
            a[1][0] += c1*v0; a[1][1] += c1*v1; a[1][2] += c1*v2;
            a[2][0] += c2*v0; a[2][1] += c2*v1; a[2][2] += c2*v2;
            dn0 += c0; dn1 += c1; dn2 += c2;
        }
        __syncthreads();
    }
    float inv0 = (1.f/3.f)/(dn0 + 1e-16f);
    float inv1 = (1.f/3.f)/(dn1 + 1e-16f);
    float inv2 = (1.f/3.f)/(dn2 + 1e-16f);
    #pragma unroll
    for (int j = 0; j < 3; j++){
        g_Z16[(size_t)n*KDIM + 0*CD + tid + 128*j] = __float2half(a[0][j]*inv0);
        g_Z16[(size_t)n*KDIM + 1*CD + tid + 128*j] = __float2half(a[1][j]*inv1);
        g_Z16[(size_t)n*KDIM + 2*CD + tid + 128*j] = __float2half(a[2][j]*inv2);
    }
}

// ---------------- GEMM via mma.sync fp16 (M-tile range param) ----------------
#define ROWP    72
#define OFF_B   18432u                // 128*72*2
#define BUF_SZ  46080u                // + 192*72*2
#define GSM_TOT (2u*BUF_SZ)           // 90 KB

__device__ __forceinline__ void gfill(unsigned sb, int tid, int buf, int kc, int m0, int n0){
    unsigned base = sb + (unsigned)buf*BUF_SZ;
    for (int u = tid; u < 2560; u += 384){
        const __half* src;
        unsigned off;
        if (u < 1024){
            int r = u >> 3, s = u & 7;
            src = g_Z16 + (size_t)(m0 + r)*KDIM + kc*64 + s*8;
            off = (unsigned)(r*ROWP + s*8)*2u;
        } else {
            int v = u - 1024;
            int r = v >> 3, s = v & 7;
            src = g_B16 + (size_t)(n0 + r)*KDIM + kc*64 + s*8;
            off = OFF_B + (unsigned)(r*ROWP + s*8)*2u;
        }
        asm volatile("cp.async.ca.shared.global [%0], [%1], 16;"
                     :: "r"(base + off), "l"(src) : "memory");
    }
    asm volatile("cp.async.commit_group;" ::: "memory");
}

__global__ void __launch_bounds__(384, 1) k_gemm_mma(const float* __restrict__ bias, int ybase){
    extern __shared__ char sm[];
    unsigned sb = smem_u32(sm);
    int tid = threadIdx.x, lane = tid & 31, w = tid >> 5;
    int m0 = (blockIdx.y + ybase)*128, n0 = blockIdx.x*192;
    int wm = (w & 3)*32, wn = (w >> 2)*64;

    float acc[2][8][4];
    #pragma unroll
    for (int i = 0; i < 2; i++)
        #pragma unroll
        for (int j = 0; j < 8; j++)
            #pragma unroll
            for (int q = 0; q < 4; q++) acc[i][j][q] = 0.f;

    gfill(sb, tid, 0, 0, m0, n0);
    for (int kc = 0; kc < 18; kc++){
        if (kc + 1 < 18){
            gfill(sb, tid, (kc+1)&1, kc+1, m0, n0);
            asm volatile("cp.async.wait_group 1;" ::: "memory");
        } else {
            asm volatile("cp.async.wait_group 0;" ::: "memory");
        }
        __syncthreads();
        unsigned base = sb + (unsigned)(kc&1)*BUF_SZ;
        #pragma unroll
        for (int ks = 0; ks < 4; ks++){
            int kk = ks*16;
            unsigned aa[2][4];
            #pragma unroll
            for (int mi = 0; mi < 2; mi++){
                int row = wm + mi*16 + (lane & 15);
                int col = kk + 8*(lane >> 4);
                LDSM4(aa[mi], base + (unsigned)(row*ROWP + col)*2u);
            }
            unsigned bb[4][4];
            #pragma unroll
            for (int p = 0; p < 4; p++){
                int row = wn + p*16 + (lane & 7) + 8*(lane >> 4);
                int col = kk + 8*((lane >> 3) & 1);
                LDSM4(bb[p], base + OFF_B + (unsigned)(row*ROWP + col)*2u);
            }
            #pragma unroll
            for (int mi = 0; mi < 2; mi++)
                #pragma unroll
                for (int nj = 0; nj < 8; nj++)
                    MMAF16(acc[mi][nj], aa[mi], (&bb[nj>>1][(nj&1)*2]));
        }
        __syncthreads();
    }

    int r0 = lane >> 2, c0 = 2*(lane & 3);
    #pragma unroll
    for (int mi = 0; mi < 2; mi++)
        #pragma unroll
        for (int nj = 0; nj < 8; nj++){
            int row = m0 + wm + mi*16 + r0;
            int col = n0 + wn + nj*8 + c0;
            float b0 = bias[col], b1 = bias[col+1];
            *(float2*)&g_gatout[(size_t)row*CD + col] =
                make_float2(acc[mi][nj][0] + b0, acc[mi][nj][1] + b1);
            *(float2*)&g_gatout[(size_t)(row+8)*CD + col] =
                make_float2(acc[mi][nj][2] + b0, acc[mi][nj][3] + b1);
        }
}

// ---------------- predictor: warp per node ----------------
__global__ void k_pred(const float* __restrict__ Wp1, const float* __restrict__ bp1,
                       const float* __restrict__ Wp3, const float* __restrict__ bp3,
                       float* __restrict__ out){
    int warp = threadIdx.x >> 5, lane = threadIdx.x & 31;
    int n = blockIdx.x*8 + warp;
    const float* row = g_gatout + (size_t)n*CD;
    float w1 = Wp1[lane];
    float b1 = bp1[0];
    float p[TT];
    #pragma unroll
    for (int t = 0; t < TT; t++){
        float s = row[t*HID + lane]*w1;
        #pragma unroll
        for (int o = 16; o; o >>= 1) s += __shfl_xor_sync(0xffffffffu, s, o);
        s += b1;
        p[t] = (s > 0.f) ? s : 0.f;
    }
    if (lane < PLEN){
        float q = bp3[lane];
        #pragma unroll
        for (int t = 0; t < TT; t++) q += p[t]*Wp3[lane*TT + t];
        out[(size_t)n*PLEN + lane] = (q > 0.f) ? q : 0.f;
    }
}

// ---------------- batch max-pool ----------------
__global__ void k_pool(const int* __restrict__ bv){
    int g0 = blockIdx.x*128;
    int c  = threadIdx.x;
    int b  = bv[g0];
    float m = -3.0e38f;
    for (int i = 0; i < 128; i++){
        float v = g_gatout[(size_t)(g0+i)*CD + c];
        m = fmaxf(m, v);
    }
    atomicMax(&g_pooled[b*CD + c], fenc(m));
}

// ---------------- classifier + softmax; resets g_pooled for next replay ----------------
__global__ void k_cls(const float* __restrict__ Wc1, const float* __restrict__ bc1,
                      const float* __restrict__ Wc2, const float* __restrict__ bc2,
                      float* __restrict__ out, int out_size){
    __shared__ float l1[NB][32];
    __shared__ float l2[NB][2];
    int tid = threadIdx.x;
    int b = tid >> 5, i = tid & 31;
    float a = bc1[i];
    for (int c = 0; c < CD; c++) a += fdec(g_pooled[b*CD + c]) * Wc1[i*CD + c];
    l1[b][i] = a;
    __syncthreads();
    unsigned neg = fenc(-3.0e38f);
    for (int q = tid; q < NB*CD; q += 256) g_pooled[q] = neg;
    if (tid < NB*2){
        int bb = tid >> 1, j = tid & 1;
        float v = bc2[j];
        for (int k = 0; k < 32; k++) v += l1[bb][k]*Wc2[j*32 + k];
        l2[bb][j] = v;
    }
    __syncthreads();
    if (tid < NB*2){
        int bb = tid >> 1, j = tid & 1;
        float m = fmaxf(l2[bb][0], l2[bb][1]);
        float e0 = __expf(l2[bb][0] - m), e1 = __expf(l2[bb][1] - m);
        out[out_size - NB*2 + bb*2 + j] = ((j == 0) ? e0 : e1) / (e0 + e1);
    }
}

// ---------------- launch: round-10 DAG, init-free, fast vecs ----------------
extern "C" void kernel_launch(void* const* d_in, const int* in_sizes, int n_in,
                              void* d_out, int out_size){
    const float* x   = (const float*)d_in[0];
    const int*   ei  = (const int*)  d_in[1];
    const float* ea  = (const float*)d_in[2];
    const int*   bv  = (const int*)  d_in[3];
    int wb = (n_in >= 23 && in_sizes[4] == 1) ? 5 : 4;
    const float* Wih      = (const float*)d_in[wb+0];
    const float* Whh      = (const float*)d_in[wb+1];
    const float* bih      = (const float*)d_in[wb+2];
    const float* bhh      = (const float*)d_in[wb+3];
    const float* Wgat     = (const float*)d_in[wb+4];
    const float* att_src  = (const float*)d_in[wb+5];
    const float* att_dst  = (const float*)d_in[wb+6];
    const float* Wedge    = (const float*)d_in[wb+7];
    const float* att_edge = (const float*)d_in[wb+8];
    const float* gat_bias = (const float*)d_in[wb+9];
    const float* Wp1      = (const float*)d_in[wb+10];
    const float* bp1      = (const float*)d_in[wb+11];
    const float* Wp3      = (const float*)d_in[wb+12];
    const float* bp3      = (const float*)d_in[wb+13];
    const float* Wc1      = (const float*)d_in[wb+14];
    const float* bc1      = (const float*)d_in[wb+15];
    const float* Wc2      = (const float*)d_in[wb+16];
    const float* bc2      = (const float*)d_in[wb+17];
    float* out = (float*)d_out;

    static cudaStream_t s2 = 0, s3 = 0;
    static cudaEvent_t evRoot = 0, evVecs = 0, evScat = 0, evB16 = 0;
    static cudaEvent_t evAgg0 = 0, evGemm0 = 0, evGemmAll = 0, evCls = 0;
    if (!s2){
        cudaStreamCreateWithFlags(&s2, cudaStreamNonBlocking);
        cudaStreamCreateWithFlags(&s3, cudaStreamNonBlocking);
        cudaEventCreateWithFlags(&evRoot,    cudaEventDisableTiming);
        cudaEventCreateWithFlags(&evVecs,    cudaEventDisableTiming);
        cudaEventCreateWithFlags(&evScat,    cudaEventDisableTiming);
        cudaEventCreateWithFlags(&evB16,     cudaEventDisableTiming);
        cudaEventCreateWithFlags(&evAgg0,    cudaEventDisableTiming);
        cudaEventCreateWithFlags(&evGemm0,   cudaEventDisableTiming);
        cudaEventCreateWithFlags(&evGemmAll, cudaEventDisableTiming);
        cudaEventCreateWithFlags(&evCls,     cudaEventDisableTiming);
        cudaFuncSetAttribute(k_gemm_mma, cudaFuncAttributeMaxDynamicSharedMemorySize, GSM_TOT);
    }

    cudaEventRecord(evRoot, 0);

    // s2: full edge sort pipeline — starts at t=0
    cudaStreamWaitEvent(s2, evRoot, 0);
    k_count<<<NE/1024, 256, 0, s2>>>(ei);
    k_scan <<<1, 1024, 0, s2>>>();
    k_scat <<<NE/256, 256, 0, s2>>>(ei, ea);
    cudaEventRecord(evScat, s2);

    // s3: coalesced vecs+kedge (no deps) -> b16 convert
    cudaStreamWaitEvent(s3, evRoot, 0);
    k_vecs_f<<<3, 768, 0, s3>>>(Wgat, att_src, att_dst, Wedge, att_edge);
    cudaEventRecord(evVecs, s3);
    k_b16   <<<(CD*KDIM + 255)/256, 256, 0, s3>>>(Wgat);
    cudaEventRecord(evB16, s3);

    // main: gru2 (needs vecs), then fused agg (needs scat)
    cudaStreamWaitEvent(0, evVecs, 0);
    k_gru2 <<<512, 128>>>(x, Wih, Whh, bih, bhh);
    cudaStreamWaitEvent(0, evScat, 0);
    k_agg3 <<<NNODES/2, 128>>>(0);
    cudaEventRecord(evAgg0, 0);
    k_agg3 <<<NNODES/2, 128>>>(NNODES/2);

    // s3: gemm lower half overlapped with agg upper half
    cudaStreamWaitEvent(s3, evAgg0, 0);
    k_gemm_mma<<<dim3(2, 32), 384, GSM_TOT, s3>>>(gat_bias, 0);
    cudaEventRecord(evGemm0, s3);

    // main: gemm upper half (needs b16)
    cudaStreamWaitEvent(0, evB16, 0);
    k_gemm_mma<<<dim3(2, 32), 384, GSM_TOT>>>(gat_bias, 32);
    cudaStreamWaitEvent(0, evGemm0, 0);
    cudaEventRecord(evGemmAll, 0);

    // s2: pool + cls after full gemm
    cudaStreamWaitEvent(s2, evGemmAll, 0);
    k_pool <<<64, 384, 0, s2>>>(bv);
    k_cls  <<<1, 256, 0, s2>>>(Wc1, bc1, Wc2, bc2, out, out_size);
    cudaEventRecord(evCls, s2);

    // main: pred, then join cls
    k_pred <<<1024, 256>>>(Wp1, bp1, Wp3, bp3, out);
    cudaStreamWaitEvent(0, evCls, 0);
}

// round 13
// speedup vs baseline: 1.1426x; 1.0713x over previous
#include <cuda_runtime.h>
#include <cuda_fp16.h>
#include <math.h>

#define NB      8
#define NODE    1024
#define TT      12
#define DIN     16
#define HID     32
#define HEADS   3
#define CD      384
#define NNODES  8192
#define NE      65536
#define PLEN    6
#define KDIM    1152        // HEADS*CD

// ---------------- scratch (static device memory) ----------------
__device__ float    g_gatin [NNODES*CD];
__device__ float    g_vsrc  [CD*HEADS];
__device__ float    g_vdst  [CD*HEADS];
__device__ float    g_kedge [HEADS];
__device__ __half   g_B16   [CD*KDIM];      // B[n][k] row-major fp16 (permuted Wgat)
__device__ float    g_asrc  [NNODES*HEADS];
__device__ float    g_adst  [NNODES*HEADS];
__device__ int      g_count [NNODES];        // static-zero; re-zeroed by k_scan each run
__device__ int      g_off   [NNODES+1];
__device__ int      g_cur   [NNODES];
__device__ float2   g_ew2   [NE];            // (src, edge_attr) sorted by dst
__device__ __half   g_Z16   [NNODES*KDIM];
__device__ float    g_gatout[NNODES*CD];
__device__ unsigned g_pooled[NB*CD] = {};    // 0 is a valid encoded-max identity; k_cls resets

__device__ __forceinline__ unsigned fenc(float f){
    unsigned u = __float_as_uint(f);
    return (u & 0x80000000u) ? ~u : (u | 0x80000000u);
}
__device__ __forceinline__ float fdec(unsigned u){
    unsigned v = (u & 0x80000000u) ? (u & 0x7fffffffu) : ~u;
    return __uint_as_float(v);
}
__device__ __forceinline__ unsigned smem_u32(const void* p){
    unsigned a;
    asm("{ .reg .u64 t; cvta.to.shared.u64 t, %1; cvt.u32.u64 %0, t; }" : "=r"(a) : "l"(p));
    return a;
}

// ---------------- mma.sync helpers ----------------
#define LDSM4(r, a)                                                                 \
    asm volatile("ldmatrix.sync.aligned.m8n8.x4.shared.b16 {%0,%1,%2,%3}, [%4];"    \
        : "=r"((r)[0]), "=r"((r)[1]), "=r"((r)[2]), "=r"((r)[3]) : "r"(a))

#define MMAF16(d, a, b)                                                             \
    asm volatile("mma.sync.aligned.m16n8k16.row.col.f32.f16.f16.f32 "               \
        "{%0,%1,%2,%3}, {%4,%5,%6,%7}, {%8,%9}, {%0,%1,%2,%3};"                     \
        : "+f"((d)[0]), "+f"((d)[1]), "+f"((d)[2]), "+f"((d)[3])                    \
        : "r"((a)[0]), "r"((a)[1]), "r"((a)[2]), "r"((a)[3]),                       \
          "r"((b)[0]), "r"((b)[1]))

// ---------------- attention projection vectors + kedge (round-10 verified, 39 blocks) --
// grid (13, 3): x<12 -> vsrc/vdst f-chunk of 32; x==12 -> kedge[h]
__global__ void __launch_bounds__(256) k_vecs_r(const float* __restrict__ Wgat,
                                                const float* __restrict__ att_src,
                                                const float* __restrict__ att_dst,
                                                const float* __restrict__ Wedge,
                                                const float* __restrict__ att_edge){
    int h = blockIdx.y;
    if (blockIdx.x == 12){
        if (threadIdx.x < 32){
            int lane = threadIdx.x;
            float s = 0.f;
            for (int c = lane; c < CD; c += 32) s += Wedge[h*CD + c]*att_edge[h*CD + c];
            #pragma unroll
            for (int o = 16; o; o >>= 1) s += __shfl_xor_sync(0xffffffffu, s, o);
            if (lane == 0) g_kedge[h] = s;
        }
        return;
    }
    __shared__ float ss[8][32], sd[8][32];
    int f0 = blockIdx.x*32;
    int lane = threadIdx.x & 31, cp = threadIdx.x >> 5;
    float as_ = 0.f, ad_ = 0.f;
    for (int c = cp; c < CD; c += 8){
        float wv = Wgat[((size_t)(h*CD + c))*CD + f0 + lane];
        as_ += wv * att_src[h*CD + c];
        ad_ += wv * att_dst[h*CD + c];
    }
    ss[cp][lane] = as_; sd[cp][lane] = ad_;
    __syncthreads();
    if (cp == 0){
        float s = 0.f, d = 0.f;
        #pragma unroll
        for (int i = 0; i < 8; i++){ s += ss[i][lane]; d += sd[i][lane]; }
        g_vsrc[(f0 + lane)*3 + h] = s;
        g_vdst[(f0 + lane)*3 + h] = d;
    }
}

// ---------------- B fp16 convert (permuted: B[c][k] = Wgat[(h*384+c)*384+f]) ------------
__global__ void k_b16(const float* __restrict__ Wgat){
    int idx = blockIdx.x*blockDim.x + threadIdx.x;
    if (idx >= CD*KDIM) return;
    int c = idx / KDIM, k = idx % KDIM;
    int h = k / CD, f = k % CD;
    g_B16[idx] = __float2half(Wgat[((size_t)(h*CD + c))*CD + f]);
}

// ---------------- GRU recurrence only — NO dependencies, starts at t=0 ----------------
__global__ void __launch_bounds__(128) k_gru2(const float* __restrict__ x,
                                              const float* __restrict__ Wih,
                                              const float* __restrict__ Whh,
                                              const float* __restrict__ bih,
                                              const float* __restrict__ bhh){
    int tid = threadIdx.x, lane = tid & 31, w = tid >> 5;
    int wg = blockIdx.x*4 + w;           // 0..2047, 4 nodes each
    float wir[16], wiz[16], win[16];
    float whr[32], whz[32], whn[32];
    #pragma unroll
    for (int d = 0; d < 16; d++){
        wir[d] = Wih[(lane)*16 + d];
        wiz[d] = Wih[(32 + lane)*16 + d];
        win[d] = Wih[(64 + lane)*16 + d];
    }
    #pragma unroll
    for (int k = 0; k < 32; k++){
        whr[k] = Whh[(lane)*32 + k];
        whz[k] = Whh[(32 + lane)*32 + k];
        whn[k] = Whh[(64 + lane)*32 + k];
    }
    float br = bih[lane] + bhh[lane];
    float bz = bih[32+lane] + bhh[32+lane];
    float bni = bih[64+lane];
    float bnh = bhh[64+lane];

    for (int ni = 0; ni < 4; ni++){
        int n = wg*4 + ni;
        float h = 0.f;
        const float* xrow = x + (size_t)n*TT*DIN;
        float* outp = g_gatin + (size_t)n*CD;
        for (int t = 0; t < TT; t++){
            float xv = (lane < DIN) ? xrow[t*DIN + lane] : 0.f;
            float gr = br, gz = bz, gn = bni;
            #pragma unroll
            for (int d = 0; d < DIN; d++){
                float xd = __shfl_sync(0xffffffffu, xv, d);
                gr += wir[d]*xd; gz += wiz[d]*xd; gn += win[d]*xd;
            }
            float ar = 0.f, az = 0.f, an = 0.f;
            #pragma unroll
            for (int k = 0; k < 32; k++){
                float hk = __shfl_sync(0xffffffffu, h, k);
                ar += whr[k]*hk; az += whz[k]*hk; an += whn[k]*hk;
            }
            float r  = 1.f/(1.f + __expf(-(gr + ar)));
            float z  = 1.f/(1.f + __expf(-(gz + az)));
            float nn = tanhf(gn + r*(an + bnh));
            h = (1.f - z)*nn + z*h;
            outp[t*32 + lane] = h;
        }
    }
}

// ---------------- per-node attention logit parts (after gru2 + vecs) ----------------
__global__ void k_asrc(){
    int warp = threadIdx.x >> 5, lane = threadIdx.x & 31;
    int n = blockIdx.x*8 + warp;
    float s0=0,s1=0,s2=0,d0=0,d1=0,d2=0;
    const float* row = g_gatin + (size_t)n*CD;
    for (int f = lane; f < CD; f += 32){
        float g = row[f];
        s0 += g*g_vsrc[f*3+0]; s1 += g*g_vsrc[f*3+1]; s2 += g*g_vsrc[f*3+2];
        d0 += g*g_vdst[f*3+0]; d1 += g*g_vdst[f*3+1]; d2 += g*g_vdst[f*3+2];
    }
    #pragma unroll
    for (int o = 16; o; o >>= 1){
        s0 += __shfl_xor_sync(0xffffffffu, s0, o);
        s1 += __shfl_xor_sync(0xffffffffu, s1, o);
        s2 += __shfl_xor_sync(0xffffffffu, s2, o);
        d0 += __shfl_xor_sync(0xffffffffu, d0, o);
        d1 += __shfl_xor_sync(0xffffffffu, d1, o);
        d2 += __shfl_xor_sync(0xffffffffu, d2, o);
    }
    if (lane == 0){
        g_asrc[n*3+0]=s0; g_asrc[n*3+1]=s1; g_asrc[n*3+2]=s2;
        g_adst[n*3+0]=d0; g_adst[n*3+1]=d1; g_adst[n*3+2]=d2;
    }
}

// ---------------- edge pipeline (runs from graph root on s2) ----------------
__global__ void k_count(const int* __restrict__ ei){
    int i = blockIdx.x*blockDim.x + threadIdx.x;
    int4 d = ((const int4*)(ei + NE))[i];
    atomicAdd(&g_count[d.x], 1);
    atomicAdd(&g_count[d.y], 1);
    atomicAdd(&g_count[d.z], 1);
    atomicAdd(&g_count[d.w], 1);
}

__global__ void k_scan(){
    __shared__ int sh[1024];
    int t = threadIdx.x;
    int loc[8];
    int base = t*8;
    int s = 0;
    #pragma unroll
    for (int i = 0; i < 8; i++){ loc[i] = s; s += g_count[base+i]; }
    sh[t] = s; __syncthreads();
    for (int off = 1; off < 1024; off <<= 1){
        int v = (t >= off) ? sh[t-off] : 0;
        __syncthreads();
        sh[t] += v;
        __syncthreads();
    }
    int excl = (t == 0) ? 0 : sh[t-1];
    #pragma unroll
    for (int i = 0; i < 8; i++){
        int o = excl + loc[i];
        g_off[base+i] = o; g_cur[base+i] = o;
        g_count[base+i] = 0;               // restore for next graph replay
    }
    if (t == 1023) g_off[NNODES] = excl + s;
}

__global__ void k_scat(const int* __restrict__ ei, const float* __restrict__ ea){
    int e = blockIdx.x*blockDim.x + threadIdx.x;
    if (e >= NE) return;
    int d = ei[NE + e];
    int pos = atomicAdd(&g_cur[d], 1);
    g_ew2[pos] = make_float2(__int_as_float(ei[e]), ea[e]);
}

// ---------------- aggregation: fused logit+exp+softmax+gather -> fp16 Z ----------------
// block = node (128 threads); thread t owns channels t, t+128, t+256. (round-10 verified)
__global__ void __launch_bounds__(128) k_agg3(int nbase){
    __shared__ float sw[32*3];
    __shared__ int   ssrc[32];
    int n = blockIdx.x + nbase;
    int tid = threadIdx.x;
    int s0 = g_off[n], s1 = g_off[n+1];
    float ad0 = g_adst[n*3+0], ad1 = g_adst[n*3+1], ad2 = g_adst[n*3+2];
    float ke0 = g_kedge[0], ke1 = g_kedge[1], ke2 = g_kedge[2];
    float a[3][3] = {};
    float dn0=0.f, dn1=0.f, dn2=0.f;

    for (int c = s0; c < s1; c += 32){
        int m = s1 - c; if (m > 32) m = 32;
        if (tid < m*3){
            int j = tid / 3, hh = tid - 3*j;
            float2 q = g_ew2[c + j];
            int src = __float_as_int(q.x);
            float ad = (hh == 0) ? ad0 : ((hh == 1) ? ad1 : ad2);
            float ke = (hh == 0) ? ke0 : ((hh == 1) ? ke1 : ke2);
            float l = g_asrc[src*3 + hh] + ad + q.y*ke;
            l = (l > 0.f) ? l : 0.2f*l;          // leaky_relu 0.2
            sw[j*3 + hh] = __expf(l);            // logits O(1): no max-shift
            if (hh == 0) ssrc[j] = src;
        }
        __syncthreads();
        for (int j = 0; j < m; j++){
            int src = ssrc[j];
            float c0 = sw[j*3+0], c1 = sw[j*3+1], c2 = sw[j*3+2];
            const float* xr = g_gatin + (size_t)src*CD;
            float v0 = xr[tid], v1 = xr[tid+128], v2 = xr[tid+256];
            a[0][0] += c0*v0; a[0][1] += c0*v1; a[0][2] += c0*v2;
            a[1][0] += c1*v0; a[1][1] += c1*v1; a[1][2] += c1*v2;
            a[2][0] += c2*v0; a[2][1] += c2*v1; a[2][2] += c2*v2;
            dn0 += c0; dn1 += c1; dn2 += c2;
        }
        __syncthreads();
    }
    float inv0 = (1.f/3.f)/(dn0 + 1e-16f);
    float inv1 = (1.f/3.f)/(dn1 + 1e-16f);
    float inv2 = (1.f/3.f)/(dn2 + 1e-16f);
    #pragma unroll
    for (int j = 0; j < 3; j++){
        g_Z16[(size_t)n*KDIM + 0*CD + tid + 128*j] = __float2half(a[0][j]*inv0);
        g_Z16[(size_t)n*KDIM + 1*CD + tid + 128*j] = __float2half(a[1][j]*inv1);
        g_Z16[(size_t)n*KDIM + 2*CD + tid + 128*j] = __float2half(a[2][j]*inv2);
    }
}

// ---------------- GEMM via mma.sync fp16 (M-tile range param) ----------------
#define ROWP    72
#define OFF_B   18432u                // 128*72*2
#define BUF_SZ  46080u                // + 192*72*2
#define GSM_TOT (2u*BUF_SZ)           // 90 KB

__device__ __forceinline__ void gfill(unsigned sb, int tid, int buf, int kc, int m0, int n0){
    unsigned base = sb + (unsigned)buf*BUF_SZ;
    for (int u = tid; u < 2560; u += 384){
        const __half* src;
        unsigned off;
        if (u < 1024){
            int r = u >> 3, s = u & 7;
            src = g_Z16 + (size_t)(m0 + r)*KDIM + kc*64 + s*8;
            off = (unsigned)(r*ROWP + s*8)*2u;
        } else {
            int v = u - 1024;
            int r = v >> 3, s = v & 7;
            src = g_B16 + (size_t)(n0 + r)*KDIM + kc*64 + s*8;
            off = OFF_B + (unsigned)(r*ROWP + s*8)*2u;
        }
        asm volatile("cp.async.ca.shared.global [%0], [%1], 16;"
                     :: "r"(base + off), "l"(src) : "memory");
    }
    asm volatile("cp.async.commit_group;" ::: "memory");
}

__global__ void __launch_bounds__(384, 1) k_gemm_mma(const float* __restrict__ bias, int ybase){
    extern __shared__ char sm[];
    unsigned sb = smem_u32(sm);
    int tid = threadIdx.x, lane = tid & 31, w = tid >> 5;
    int m0 = (blockIdx.y + ybase)*128, n0 = blockIdx.x*192;
    int wm = (w & 3)*32, wn = (w >> 2)*64;

    float acc[2][8][4];
    #pragma unroll
    for (int i = 0; i < 2; i++)
        #pragma unroll
        for (int j = 0; j < 8; j++)
            #pragma unroll
            for (int q = 0; q < 4; q++) acc[i][j][q] = 0.f;

    gfill(sb, tid, 0, 0, m0, n0);
    for (int kc = 0; kc < 18; kc++){
        if (kc + 1 < 18){
            gfill(sb, tid, (kc+1)&1, kc+1, m0, n0);
            asm volatile("cp.async.wait_group 1;" ::: "memory");
        } else {
            asm volatile("cp.async.wait_group 0;" ::: "memory");
        }
        __syncthreads();
        unsigned base = sb + (unsigned)(kc&1)*BUF_SZ;
        #pragma unroll
        for (int ks = 0; ks < 4; ks++){
            int kk = ks*16;
            unsigned aa[2][4];
            #pragma unroll
            for (int mi = 0; mi < 2; mi++){
                int row = wm + mi*16 + (lane & 15);
                int col = kk + 8*(lane >> 4);
                LDSM4(aa[mi], base + (unsigned)(row*ROWP + col)*2u);
            }
            unsigned bb[4][4];
            #pragma unroll
            for (int p = 0; p < 4; p++){
                int row = wn + p*16 + (lane & 7) + 8*(lane >> 4);
                int col = kk + 8*((lane >> 3) & 1);
                LDSM4(bb[p], base + OFF_B + (unsigned)(row*ROWP + col)*2u);
            }
            #pragma unroll
            for (int mi = 0; mi < 2; mi++)
                #pragma unroll
                for (int nj = 0; nj < 8; nj++)
                    MMAF16(acc[mi][nj], aa[mi], (&bb[nj>>1][(nj&1)*2]));
        }
        __syncthreads();
    }

    int r0 = lane >> 2, c0 = 2*(lane & 3);
    #pragma unroll
    for (int mi = 0; mi < 2; mi++)
        #pragma unroll
        for (int nj = 0; nj < 8; nj++){
            int row = m0 + wm + mi*16 + r0;
            int col = n0 + wn + nj*8 + c0;
            float b0 = bias[col], b1 = bias[col+1];
            *(float2*)&g_gatout[(size_t)row*CD + col] =
                make_float2(acc[mi][nj][0] + b0, acc[mi][nj][1] + b1);
            *(float2*)&g_gatout[(size_t)(row+8)*CD + col] =
                make_float2(acc[mi][nj][2] + b0, acc[mi][nj][3] + b1);
        }
}

// ---------------- predictor: warp per node ----------------
__global__ void k_pred(const float* __restrict__ Wp1, const float* __restrict__ bp1,
                       const float* __restrict__ Wp3, const float* __restrict__ bp3,
                       float* __restrict__ out){
    int warp = threadIdx.x >> 5, lane = threadIdx.x & 31;
    int n = blockIdx.x*8 + warp;
    const float* row = g_gatout + (size_t)n*CD;
    float w1 = Wp1[lane];
    float b1 = bp1[0];
    float p[TT];
    #pragma unroll
    for (int t = 0; t < TT; t++){
        float s = row[t*HID + lane]*w1;
        #pragma unroll
        for (int o = 16; o; o >>= 1) s += __shfl_xor_sync(0xffffffffu, s, o);
        s += b1;
        p[t] = (s > 0.f) ? s : 0.f;
    }
    if (lane < PLEN){
        float q = bp3[lane];
        #pragma unroll
        for (int t = 0; t < TT; t++) q += p[t]*Wp3[lane*TT + t];
        out[(size_t)n*PLEN + lane] = (q > 0.f) ? q : 0.f;
    }
}

// ---------------- batch max-pool ----------------
__global__ void k_pool(const int* __restrict__ bv){
    int g0 = blockIdx.x*128;
    int c  = threadIdx.x;
    int b  = bv[g0];
    float m = -3.0e38f;
    for (int i = 0; i < 128; i++){
        float v = g_gatout[(size_t)(g0+i)*CD + c];
        m = fmaxf(m, v);
    }
    atomicMax(&g_pooled[b*CD + c], fenc(m));
}

// ---------------- classifier + softmax; resets g_pooled for next replay ----------------
__global__ void k_cls(const float* __restrict__ Wc1, const float* __restrict__ bc1,
                      const float* __restrict__ Wc2, const float* __restrict__ bc2,
                      float* __restrict__ out, int out_size){
    __shared__ float l1[NB][32];
    __shared__ float l2[NB][2];
    int tid = threadIdx.x;
    int b = tid >> 5, i = tid & 31;
    float a = bc1[i];
    for (int c = 0; c < CD; c++) a += fdec(g_pooled[b*CD + c]) * Wc1[i*CD + c];
    l1[b][i] = a;
    __syncthreads();
    unsigned neg = fenc(-3.0e38f);
    for (int q = tid; q < NB*CD; q += 256) g_pooled[q] = neg;
    if (tid < NB*2){
        int bb = tid >> 1, j = tid & 1;
        float v = bc2[j];
        for (int k = 0; k < 32; k++) v += l1[bb][k]*Wc2[j*32 + k];
        l2[bb][j] = v;
    }
    __syncthreads();
    if (tid < NB*2){
        int bb = tid >> 1, j = tid & 1;
        float m = fmaxf(l2[bb][0], l2[bb][1]);
        float e0 = __expf(l2[bb][0] - m), e1 = __expf(l2[bb][1] - m);
        out[out_size - NB*2 + bb*2 + j] = ((j == 0) ? e0 : e1) / (e0 + e1);
    }
}

// ---------------- launch: gru2 starts at t=0; vecs hidden under it ----------------
extern "C" void kernel_launch(void* const* d_in, const int* in_sizes, int n_in,
                              void* d_out, int out_size){
    const float* x   = (const float*)d_in[0];
    const int*   ei  = (const int*)  d_in[1];
    const float* ea  = (const float*)d_in[2];
    const int*   bv  = (const int*)  d_in[3];
    int wb = (n_in >= 23 && in_sizes[4] == 1) ? 5 : 4;
    const float* Wih      = (const float*)d_in[wb+0];
    const float* Whh      = (const float*)d_in[wb+1];
    const float* bih      = (const float*)d_in[wb+2];
    const float* bhh      = (const float*)d_in[wb+3];
    const float* Wgat     = (const float*)d_in[wb+4];
    const float* att_src  = (const float*)d_in[wb+5];
    const float* att_dst  = (const float*)d_in[wb+6];
    const float* Wedge    = (const float*)d_in[wb+7];
    const float* att_edge = (const float*)d_in[wb+8];
    const float* gat_bias = (const float*)d_in[wb+9];
    const float* Wp1      = (const float*)d_in[wb+10];
    const float* bp1      = (const float*)d_in[wb+11];
    const float* Wp3      = (const float*)d_in[wb+12];
    const float* bp3      = (const float*)d_in[wb+13];
    const float* Wc1      = (const float*)d_in[wb+14];
    const float* bc1      = (const float*)d_in[wb+15];
    const float* Wc2      = (const float*)d_in[wb+16];
    const float* bc2      = (const float*)d_in[wb+17];
    float* out = (float*)d_out;

    static cudaStream_t s2 = 0, s3 = 0;
    static cudaEvent_t evRoot = 0, evVecs = 0, evScat = 0, evB16 = 0;
    static cudaEvent_t evAgg0 = 0, evGemm0 = 0, evGemmAll = 0, evCls = 0;
    if (!s2){
        cudaStreamCreateWithFlags(&s2, cudaStreamNonBlocking);
        cudaStreamCreateWithFlags(&s3, cudaStreamNonBlocking);
        cudaEventCreateWithFlags(&evRoot,    cudaEventDisableTiming);
        cudaEventCreateWithFlags(&evVecs,    cudaEventDisableTiming);
        cudaEventCreateWithFlags(&evScat,    cudaEventDisableTiming);
        cudaEventCreateWithFlags(&evB16,     cudaEventDisableTiming);
        cudaEventCreateWithFlags(&evAgg0,    cudaEventDisableTiming);
        cudaEventCreateWithFlags(&evGemm0,   cudaEventDisableTiming);
        cudaEventCreateWithFlags(&evGemmAll, cudaEventDisableTiming);
        cudaEventCreateWithFlags(&evCls,     cudaEventDisableTiming);
        cudaFuncSetAttribute(k_gemm_mma, cudaFuncAttributeMaxDynamicSharedMemorySize, GSM_TOT);
    }

    cudaEventRecord(evRoot, 0);

    // s2: full edge sort pipeline — starts at t=0
    cudaStreamWaitEvent(s2, evRoot, 0);
    k_count<<<NE/1024, 256, 0, s2>>>(ei);
    k_scan <<<1, 1024, 0, s2>>>();
    k_scat <<<NE/256, 256, 0, s2>>>(ei, ea);
    cudaEventRecord(evScat, s2);

    // s3: vecs+kedge (no deps, hidden under gru2) -> b16 convert
    cudaStreamWaitEvent(s3, evRoot, 0);
    k_vecs_r<<<dim3(13, 3), 256, 0, s3>>>(Wgat, att_src, att_dst, Wedge, att_edge);
    cudaEventRecord(evVecs, s3);
    k_b16   <<<(CD*KDIM + 255)/256, 256, 0, s3>>>(Wgat);
    cudaEventRecord(evB16, s3);

    // main: gru2 at t=0 (no deps!), then asrc (needs vecs), then fused agg (needs scat)
    k_gru2 <<<512, 128>>>(x, Wih, Whh, bih, bhh);
    cudaStreamWaitEvent(0, evVecs, 0);
    k_asrc <<<1024, 256>>>();
    cudaStreamWaitEvent(0, evScat, 0);
    k_agg3 <<<NNODES/2, 128>>>(0);
    cudaEventRecord(evAgg0, 0);
    k_agg3 <<<NNODES/2, 128>>>(NNODES/2);

    // s3: gemm lower half overlapped with agg upper half
    cudaStreamWaitEvent(s3, evAgg0, 0);
    k_gemm_mma<<<dim3(2, 32), 384, GSM_TOT, s3>>>(gat_bias, 0);
    cudaEventRecord(evGemm0, s3);

    // main: gemm upper half (needs b16)
    cudaStreamWaitEvent(0, evB16, 0);
    k_gemm_mma<<<dim3(2, 32), 384, GSM_TOT>>>(gat_bias, 32);
    cudaStreamWaitEvent(0, evGemm0, 0);
    cudaEventRecord(evGemmAll, 0);

    // s2: pool + cls after full gemm
    cudaStreamWaitEvent(s2, evGemmAll, 0);
    k_pool <<<64, 384, 0, s2>>>(bv);
    k_cls  <<<1, 256, 0, s2>>>(Wc1, bc1, Wc2, bc2, out, out_size);
    cudaEventRecord(evCls, s2);

    // main: pred, then join cls
    k_pred <<<1024, 256>>>(Wp1, bp1, Wp3, bp3, out);
    cudaStreamWaitEvent(0, evCls, 0);
}

// round 14
// speedup vs baseline: 1.1915x; 1.0428x over previous
#include <cuda_runtime.h>
#include <cuda_fp16.h>
#include <math.h>

#define NB      8
#define NODE    1024
#define TT      12
#define DIN     16
#define HID     32
#define HEADS   3
#define CD      384
#define NNODES  8192
#define NE      65536
#define PLEN    6
#define KDIM    1152        // HEADS*CD

// ---------------- scratch (static device memory) ----------------
__device__ float    g_gatin [NNODES*CD];
__device__ float    g_vsrc  [CD*HEADS];
__device__ float    g_vdst  [CD*HEADS];
__device__ float    g_kedge [HEADS];
__device__ __half   g_B16   [CD*KDIM];      // B[n][k] row-major fp16 (permuted Wgat)
__device__ float    g_asrc  [NNODES*HEADS];
__device__ float    g_adst  [NNODES*HEADS];
__device__ int      g_count [NNODES];        // static-zero; re-zeroed by k_scan each run
__device__ int      g_off   [NNODES+1];
__device__ int      g_cur   [NNODES];
__device__ float2   g_ew2   [NE];            // (src, edge_attr) sorted by dst
__device__ __half   g_Z16   [NNODES*KDIM];
__device__ float    g_ps    [NNODES*TT];     // pred stage-1 sums (pre-bp1)
__device__ unsigned g_pooled[NB*CD] = {};    // 0 is a valid encoded-max identity; k_cls resets

__device__ __forceinline__ unsigned fenc(float f){
    unsigned u = __float_as_uint(f);
    return (u & 0x80000000u) ? ~u : (u | 0x80000000u);
}
__device__ __forceinline__ float fdec(unsigned u){
    unsigned v = (u & 0x80000000u) ? (u & 0x7fffffffu) : ~u;
    return __uint_as_float(v);
}
__device__ __forceinline__ unsigned smem_u32(const void* p){
    unsigned a;
    asm("{ .reg .u64 t; cvta.to.shared.u64 t, %1; cvt.u32.u64 %0, t; }" : "=r"(a) : "l"(p));
    return a;
}

// ---------------- mma.sync helpers ----------------
#define LDSM4(r, a)                                                                 \
    asm volatile("ldmatrix.sync.aligned.m8n8.x4.shared.b16 {%0,%1,%2,%3}, [%4];"    \
        : "=r"((r)[0]), "=r"((r)[1]), "=r"((r)[2]), "=r"((r)[3]) : "r"(a))

#define MMAF16(d, a, b)                                                             \
    asm volatile("mma.sync.aligned.m16n8k16.row.col.f32.f16.f16.f32 "               \
        "{%0,%1,%2,%3}, {%4,%5,%6,%7}, {%8,%9}, {%0,%1,%2,%3};"                     \
        : "+f"((d)[0]), "+f"((d)[1]), "+f"((d)[2]), "+f"((d)[3])                    \
        : "r"((a)[0]), "r"((a)[1]), "r"((a)[2]), "r"((a)[3]),                       \
          "r"((b)[0]), "r"((b)[1]))

// ---------------- attention projection vectors + kedge (verified, 39 blocks) ----------
__global__ void __launch_bounds__(256) k_vecs_r(const float* __restrict__ Wgat,
                                                const float* __restrict__ att_src,
                                                const float* __restrict__ att_dst,
                                                const float* __restrict__ Wedge,
                                                const float* __restrict__ att_edge){
    int h = blockIdx.y;
    if (blockIdx.x == 12){
        if (threadIdx.x < 32){
            int lane = threadIdx.x;
            float s = 0.f;
            for (int c = lane; c < CD; c += 32) s += Wedge[h*CD + c]*att_edge[h*CD + c];
            #pragma unroll
            for (int o = 16; o; o >>= 1) s += __shfl_xor_sync(0xffffffffu, s, o);
            if (lane == 0) g_kedge[h] = s;
        }
        return;
    }
    __shared__ float ss[8][32], sd[8][32];
    int f0 = blockIdx.x*32;
    int lane = threadIdx.x & 31, cp = threadIdx.x >> 5;
    float as_ = 0.f, ad_ = 0.f;
    for (int c = cp; c < CD; c += 8){
        float wv = Wgat[((size_t)(h*CD + c))*CD + f0 + lane];
        as_ += wv * att_src[h*CD + c];
        ad_ += wv * att_dst[h*CD + c];
    }
    ss[cp][lane] = as_; sd[cp][lane] = ad_;
    __syncthreads();
    if (cp == 0){
        float s = 0.f, d = 0.f;
        #pragma unroll
        for (int i = 0; i < 8; i++){ s += ss[i][lane]; d += sd[i][lane]; }
        g_vsrc[(f0 + lane)*3 + h] = s;
        g_vdst[(f0 + lane)*3 + h] = d;
    }
}

// ---------------- B fp16 convert (permuted: B[c][k] = Wgat[(h*384+c)*384+f]) ------------
__global__ void k_b16(const float* __restrict__ Wgat){
    int idx = blockIdx.x*blockDim.x + threadIdx.x;
    if (idx >= CD*KDIM) return;
    int c = idx / KDIM, k = idx % KDIM;
    int h = k / CD, f = k % CD;
    g_B16[idx] = __float2half(Wgat[((size_t)(h*CD + c))*CD + f]);
}

// ---------------- GRU recurrence only — NO dependencies, starts at t=0 ----------------
__global__ void __launch_bounds__(128) k_gru2(const float* __restrict__ x,
                                              const float* __restrict__ Wih,
                                              const float* __restrict__ Whh,
                                              const float* __restrict__ bih,
                                              const float* __restrict__ bhh){
    int tid = threadIdx.x, lane = tid & 31, w = tid >> 5;
    int wg = blockIdx.x*4 + w;           // 0..2047, 4 nodes each
    float wir[16], wiz[16], win[16];
    float whr[32], whz[32], whn[32];
    #pragma unroll
    for (int d = 0; d < 16; d++){
        wir[d] = Wih[(lane)*16 + d];
        wiz[d] = Wih[(32 + lane)*16 + d];
        win[d] = Wih[(64 + lane)*16 + d];
    }
    #pragma unroll
    for (int k = 0; k < 32; k++){
        whr[k] = Whh[(lane)*32 + k];
        whz[k] = Whh[(32 + lane)*32 + k];
        whn[k] = Whh[(64 + lane)*32 + k];
    }
    float br = bih[lane] + bhh[lane];
    float bz = bih[32+lane] + bhh[32+lane];
    float bni = bih[64+lane];
    float bnh = bhh[64+lane];

    for (int ni = 0; ni < 4; ni++){
        int n = wg*4 + ni;
        float h = 0.f;
        const float* xrow = x + (size_t)n*TT*DIN;
        float* outp = g_gatin + (size_t)n*CD;
        for (int t = 0; t < TT; t++){
            float xv = (lane < DIN) ? xrow[t*DIN + lane] : 0.f;
            float gr = br, gz = bz, gn = bni;
            #pragma unroll
            for (int d = 0; d < DIN; d++){
                float xd = __shfl_sync(0xffffffffu, xv, d);
                gr += wir[d]*xd; gz += wiz[d]*xd; gn += win[d]*xd;
            }
            float ar = 0.f, az = 0.f, an = 0.f;
            #pragma unroll
            for (int k = 0; k < 32; k++){
                float hk = __shfl_sync(0xffffffffu, h, k);
                ar += whr[k]*hk; az += whz[k]*hk; an += whn[k]*hk;
            }
            float r  = 1.f/(1.f + __expf(-(gr + ar)));
            float z  = 1.f/(1.f + __expf(-(gz + az)));
            float nn = tanhf(gn + r*(an + bnh));
            h = (1.f - z)*nn + z*h;
            outp[t*32 + lane] = h;
        }
    }
}

// ---------------- per-node attention logit parts (after gru2 + vecs) ----------------
__global__ void k_asrc(){
    int warp = threadIdx.x >> 5, lane = threadIdx.x & 31;
    int n = blockIdx.x*8 + warp;
    float s0=0,s1=0,s2=0,d0=0,d1=0,d2=0;
    const float* row = g_gatin + (size_t)n*CD;
    for (int f = lane; f < CD; f += 32){
        float g = row[f];
        s0 += g*g_vsrc[f*3+0]; s1 += g*g_vsrc[f*3+1]; s2 += g*g_vsrc[f*3+2];
        d0 += g*g_vdst[f*3+0]; d1 += g*g_vdst[f*3+1]; d2 += g*g_vdst[f*3+2];
    }
    #pragma unroll
    for (int o = 16; o; o >>= 1){
        s0 += __shfl_xor_sync(0xffffffffu, s0, o);
        s1 += __shfl_xor_sync(0xffffffffu, s1, o);
        s2 += __shfl_xor_sync(0xffffffffu, s2, o);
        d0 += __shfl_xor_sync(0xffffffffu, d0, o);
        d1 += __shfl_xor_sync(0xffffffffu, d1, o);
        d2 += __shfl_xor_sync(0xffffffffu, d2, o);
    }
    if (lane == 0){
        g_asrc[n*3+0]=s0; g_asrc[n*3+1]=s1; g_asrc[n*3+2]=s2;
        g_adst[n*3+0]=d0; g_adst[n*3+1]=d1; g_adst[n*3+2]=d2;
    }
}

// ---------------- edge pipeline (runs from graph root on s2) ----------------
__global__ void k_count(const int* __restrict__ ei){
    int i = blockIdx.x*blockDim.x + threadIdx.x;
    int4 d = ((const int4*)(ei + NE))[i];
    atomicAdd(&g_count[d.x], 1);
    atomicAdd(&g_count[d.y], 1);
    atomicAdd(&g_count[d.z], 1);
    atomicAdd(&g_count[d.w], 1);
}

__global__ void k_scan(){
    __shared__ int sh[1024];
    int t = threadIdx.x;
    int loc[8];
    int base = t*8;
    int s = 0;
    #pragma unroll
    for (int i = 0; i < 8; i++){ loc[i] = s; s += g_count[base+i]; }
    sh[t] = s; __syncthreads();
    for (int off = 1; off < 1024; off <<= 1){
        int v = (t >= off) ? sh[t-off] : 0;
        __syncthreads();
        sh[t] += v;
        __syncthreads();
    }
    int excl = (t == 0) ? 0 : sh[t-1];
    #pragma unroll
    for (int i = 0; i < 8; i++){
        int o = excl + loc[i];
        g_off[base+i] = o; g_cur[base+i] = o;
        g_count[base+i] = 0;               // restore for next graph replay
    }
    if (t == 1023) g_off[NNODES] = excl + s;
}

__global__ void k_scat(const int* __restrict__ ei, const float* __restrict__ ea){
    int e = blockIdx.x*blockDim.x + threadIdx.x;
    if (e >= NE) return;
    int d = ei[NE + e];
    int pos = atomicAdd(&g_cur[d], 1);
    g_ew2[pos] = make_float2(__int_as_float(ei[e]), ea[e]);
}

// ---------------- aggregation: fused logit+exp+softmax+gather -> fp16 Z ----------------
__global__ void __launch_bounds__(128) k_agg3(int nbase){
    __shared__ float sw[32*3];
    __shared__ int   ssrc[32];
    int n = blockIdx.x + nbase;
    int tid = threadIdx.x;
    int s0 = g_off[n], s1 = g_off[n+1];
    float ad0 = g_adst[n*3+0], ad1 = g_adst[n*3+1], ad2 = g_adst[n*3+2];
    float ke0 = g_kedge[0], ke1 = g_kedge[1], ke2 = g_kedge[2];
    float a[3][3] = {};
    float dn0=0.f, dn1=0.f, dn2=0.f;

    for (int c = s0; c < s1; c += 32){
        int m = s1 - c; if (m > 32) m = 32;
        if (tid < m*3){
            int j = tid / 3, hh = tid - 3*j;
            float2 q = g_ew2[c + j];
            int src = __float_as_int(q.x);
            float ad = (hh == 0) ? ad0 : ((hh == 1) ? ad1 : ad2);
            float ke = (hh == 0) ? ke0 : ((hh == 1) ? ke1 : ke2);
            float l = g_asrc[src*3 + hh] + ad + q.y*ke;
            l = (l > 0.f) ? l : 0.2f*l;          // leaky_relu 0.2
            sw[j*3 + hh] = __expf(l);            // logits O(1): no max-shift
            if (hh == 0) ssrc[j] = src;
        }
        __syncthreads();
        for (int j = 0; j < m; j++){
            int src = ssrc[j];
            float c0 = sw[j*3+0], c1 = sw[j*3+1], c2 = sw[j*3+2];
            const float* xr = g_gatin + (size_t)src*CD;
            float v0 = xr[tid], v1 = xr[tid+128], v2 = xr[tid+256];
            a[0][0] += c0*v0; a[0][1] += c0*v1; a[0][2] += c0*v2;
            a[1][0] += c1*v0; a[1][1] += c1*v1; a[1][2] += c1*v2;
            a[2][0] += c2*v0; a[2][1] += c2*v1; a[2][2] += c2*v2;
            dn0 += c0; dn1 += c1; dn2 += c2;
        }
        __syncthreads();
    }
    float inv0 = (1.f/3.f)/(dn0 + 1e-16f);
    float inv1 = (1.f/3.f)/(dn1 + 1e-16f);
    float inv2 = (1.f/3.f)/(dn2 + 1e-16f);
    #pragma unroll
    for (int j = 0; j < 3; j++){
        g_Z16[(size_t)n*KDIM + 0*CD + tid + 128*j] = __float2half(a[0][j]*inv0);
        g_Z16[(size_t)n*KDIM + 1*CD + tid + 128*j] = __float2half(a[1][j]*inv1);
        g_Z16[(size_t)n*KDIM + 2*CD + tid + 128*j] = __float2half(a[2][j]*inv2);
    }
}

// ---------------- GEMM + fused epilogue: pred chunk sums + batch max-pool --------------
// No gatout materialization. ps[n][t] = sum_o (gemm+bias)[n][t*32+o]*Wp1[o];
// pooled[b][c] = max over batch (atomicMax, all 128 CTA rows share one batch).
#define ROWP    72
#define OFF_B   18432u                // 128*72*2
#define BUF_SZ  46080u                // + 192*72*2
#define GSM_TOT (2u*BUF_SZ)           // 90 KB

__device__ __forceinline__ void gfill(unsigned sb, int tid, int buf, int kc, int m0, int n0){
    unsigned base = sb + (unsigned)buf*BUF_SZ;
    for (int u = tid; u < 2560; u += 384){
        const __half* src;
        unsigned off;
        if (u < 1024){
            int r = u >> 3, s = u & 7;
            src = g_Z16 + (size_t)(m0 + r)*KDIM + kc*64 + s*8;
            off = (unsigned)(r*ROWP + s*8)*2u;
        } else {
            int v = u - 1024;
            int r = v >> 3, s = v & 7;
            src = g_B16 + (size_t)(n0 + r)*KDIM + kc*64 + s*8;
            off = OFF_B + (unsigned)(r*ROWP + s*8)*2u;
        }
        asm volatile("cp.async.ca.shared.global [%0], [%1], 16;"
                     :: "r"(base + off), "l"(src) : "memory");
    }
    asm volatile("cp.async.commit_group;" ::: "memory");
}

__global__ void __launch_bounds__(384, 1) k_gemm_mma(const float* __restrict__ bias,
                                                     const float* __restrict__ Wp1,
                                                     int ybase){
    extern __shared__ char sm[];
    unsigned sb = smem_u32(sm);
    int tid = threadIdx.x, lane = tid & 31, w = tid >> 5;
    int m0 = (blockIdx.y + ybase)*128, n0 = blockIdx.x*192;
    int wm = (w & 3)*32, wn = (w >> 2)*64;

    float acc[2][8][4];
    #pragma unroll
    for (int i = 0; i < 2; i++)
        #pragma unroll
        for (int j = 0; j < 8; j++)
            #pragma unroll
            for (int q = 0; q < 4; q++) acc[i][j][q] = 0.f;

    gfill(sb, tid, 0, 0, m0, n0);
    for (int kc = 0; kc < 18; kc++){
        if (kc + 1 < 18){
            gfill(sb, tid, (kc+1)&1, kc+1, m0, n0);
            asm volatile("cp.async.wait_group 1;" ::: "memory");
        } else {
            asm volatile("cp.async.wait_group 0;" ::: "memory");
        }
        __syncthreads();
        unsigned base = sb + (unsigned)(kc&1)*BUF_SZ;
        #pragma unroll
        for (int ks = 0; ks < 4; ks++){
            int kk = ks*16;
            unsigned aa[2][4];
            #pragma unroll
            for (int mi = 0; mi < 2; mi++){
                int row = wm + mi*16 + (lane & 15);
                int col = kk + 8*(lane >> 4);
                LDSM4(aa[mi], base + (unsigned)(row*ROWP + col)*2u);
            }
            unsigned bb[4][4];
            #pragma unroll
            for (int p = 0; p < 4; p++){
                int row = wn + p*16 + (lane & 7) + 8*(lane >> 4);
                int col = kk + 8*((lane >> 3) & 1);
                LDSM4(bb[p], base + OFF_B + (unsigned)(row*ROWP + col)*2u);
            }
            #pragma unroll
            for (int mi = 0; mi < 2; mi++)
                #pragma unroll
                for (int nj = 0; nj < 8; nj++)
                    MMAF16(acc[mi][nj], aa[mi], (&bb[nj>>1][(nj&1)*2]));
        }
        __syncthreads();
    }

    // ---- fused epilogue ----
    int r0 = lane >> 2, c0 = 2*(lane & 3);
    int b = m0 >> 10;                     // batch of all 128 rows in this CTA
    float psum[2][2][2] = {};             // [mi][chunk-half][row: r0 / r0+8]
    float cmax[8][2];                     // per-col max over this thread's 4 rows
    #pragma unroll
    for (int nj = 0; nj < 8; nj++){ cmax[nj][0] = -3.0e38f; cmax[nj][1] = -3.0e38f; }

    #pragma unroll
    for (int mi = 0; mi < 2; mi++)
        #pragma unroll
        for (int nj = 0; nj < 8; nj++){
            int col = n0 + wn + nj*8 + c0;
            float b0 = bias[col], b1v = bias[col+1];
            float w1a = Wp1[col & 31], w1b = Wp1[(col+1) & 31];
            float v0 = acc[mi][nj][0] + b0, v1 = acc[mi][nj][1] + b1v;   // row r0
            float v2 = acc[mi][nj][2] + b0, v3 = acc[mi][nj][3] + b1v;   // row r0+8
            int half = nj >> 2;
            psum[mi][half][0] += v0*w1a + v1*w1b;
            psum[mi][half][1] += v2*w1a + v3*w1b;
            cmax[nj][0] = fmaxf(cmax[nj][0], fmaxf(v0, v2));
            cmax[nj][1] = fmaxf(cmax[nj][1], fmaxf(v1, v3));
        }

    // pred chunk sums: reduce over quad (lane^1, lane^2), write g_ps
    #pragma unroll
    for (int mi = 0; mi < 2; mi++)
        #pragma unroll
        for (int half = 0; half < 2; half++)
            #pragma unroll
            for (int rr = 0; rr < 2; rr++){
                float v = psum[mi][half][rr];
                v += __shfl_xor_sync(0xffffffffu, v, 1);
                v += __shfl_xor_sync(0xffffffffu, v, 2);
                if ((lane & 3) == 0){
                    int row = m0 + wm + mi*16 + r0 + rr*8;
                    int tch = ((n0 + wn) >> 5) + half;
                    g_ps[row*TT + tch] = v;
                }
            }

    // pool: reduce over the warp's 32 rows (lane^4, ^8, ^16), atomicMax per column
    #pragma unroll
    for (int nj = 0; nj < 8; nj++)
        #pragma unroll
        for (int q = 0; q < 2; q++){
            float v = cmax[nj][q];
            v = fmaxf(v, __shfl_xor_sync(0xffffffffu, v, 4));
            v = fmaxf(v, __shfl_xor_sync(0xffffffffu, v, 8));
            v = fmaxf(v, __shfl_xor_sync(0xffffffffu, v, 16));
            if (lane < 4){
                int col = n0 + wn + nj*8 + c0 + q;
                atomicMax(&g_pooled[b*CD + col], fenc(v));
            }
        }
}

// ---------------- predictor stage 2: tiny (reads g_ps only) ----------------
__global__ void k_pred2(const float* __restrict__ bp1, const float* __restrict__ Wp3,
                        const float* __restrict__ bp3, float* __restrict__ out){
    int n = blockIdx.x*256 + threadIdx.x;
    float b1 = bp1[0];
    float p[TT];
    #pragma unroll
    for (int t = 0; t < TT; t++){
        float v = g_ps[n*TT + t] + b1;
        p[t] = (v > 0.f) ? v : 0.f;
    }
    #pragma unroll
    for (int j = 0; j < PLEN; j++){
        float q = bp3[j];
        #pragma unroll
        for (int t = 0; t < TT; t++) q += p[t]*Wp3[j*TT + t];
        out[(size_t)n*PLEN + j] = (q > 0.f) ? q : 0.f;
    }
}

// ---------------- classifier + softmax; resets g_pooled for next replay ----------------
__global__ void k_cls(const float* __restrict__ Wc1, const float* __restrict__ bc1,
                      const float* __restrict__ Wc2, const float* __restrict__ bc2,
                      float* __restrict__ out, int out_size){
    __shared__ float l1[NB][32];
    __shared__ float l2[NB][2];
    int tid = threadIdx.x;
    int b = tid >> 5, i = tid & 31;
    float a = bc1[i];
    for (int c = 0; c < CD; c++) a += fdec(g_pooled[b*CD + c]) * Wc1[i*CD + c];
    l1[b][i] = a;
    __syncthreads();
    unsigned neg = fenc(-3.0e38f);
    for (int q = tid; q < NB*CD; q += 256) g_pooled[q] = neg;
    if (tid < NB*2){
        int bb = tid >> 1, j = tid & 1;
        float v = bc2[j];
        for (int k = 0; k < 32; k++) v += l1[bb][k]*Wc2[j*32 + k];
        l2[bb][j] = v;
    }
    __syncthreads();
    if (tid < NB*2){
        int bb = tid >> 1, j = tid & 1;
        float m = fmaxf(l2[bb][0], l2[bb][1]);
        float e0 = __expf(l2[bb][0] - m), e1 = __expf(l2[bb][1] - m);
        out[out_size - NB*2 + bb*2 + j] = ((j == 0) ? e0 : e1) / (e0 + e1);
    }
}

// ---------------- launch ----------------
extern "C" void kernel_launch(void* const* d_in, const int* in_sizes, int n_in,
                              void* d_out, int out_size){
    const float* x   = (const float*)d_in[0];
    const int*   ei  = (const int*)  d_in[1];
    const float* ea  = (const float*)d_in[2];
    int wb = (n_in >= 23 && in_sizes[4] == 1) ? 5 : 4;
    const float* Wih      = (const float*)d_in[wb+0];
    const float* Whh      = (const float*)d_in[wb+1];
    const float* bih      = (const float*)d_in[wb+2];
    const float* bhh      = (const float*)d_in[wb+3];
    const float* Wgat     = (const float*)d_in[wb+4];
    const float* att_src  = (const float*)d_in[wb+5];
    const float* att_dst  = (const float*)d_in[wb+6];
    const float* Wedge    = (const float*)d_in[wb+7];
    const float* att_edge = (const float*)d_in[wb+8];
    const float* gat_bias = (const float*)d_in[wb+9];
    const float* Wp1      = (const float*)d_in[wb+10];
    const float* bp1      = (const float*)d_in[wb+11];
    const float* Wp3      = (const float*)d_in[wb+12];
    const float* bp3      = (const float*)d_in[wb+13];
    const float* Wc1      = (const float*)d_in[wb+14];
    const float* bc1      = (const float*)d_in[wb+15];
    const float* Wc2      = (const float*)d_in[wb+16];
    const float* bc2      = (const float*)d_in[wb+17];
    float* out = (float*)d_out;

    static cudaStream_t s2 = 0, s3 = 0;
    static cudaEvent_t evRoot = 0, evVecs = 0, evScat = 0, evB16 = 0;
    static cudaEvent_t evAgg0 = 0, evGemm0 = 0, evGemmAll = 0, evCls = 0;
    if (!s2){
        cudaStreamCreateWithFlags(&s2, cudaStreamNonBlocking);
        cudaStreamCreateWithFlags(&s3, cudaStreamNonBlocking);
        cudaEventCreateWithFlags(&evRoot,    cudaEventDisableTiming);
        cudaEventCreateWithFlags(&evVecs,    cudaEventDisableTiming);
        cudaEventCreateWithFlags(&evScat,    cudaEventDisableTiming);
        cudaEventCreateWithFlags(&evB16,     cudaEventDisableTiming);
        cudaEventCreateWithFlags(&evAgg0,    cudaEventDisableTiming);
        cudaEventCreateWithFlags(&evGemm0,   cudaEventDisableTiming);
        cudaEventCreateWithFlags(&evGemmAll, cudaEventDisableTiming);
        cudaEventCreateWithFlags(&evCls,     cudaEventDisableTiming);
        cudaFuncSetAttribute(k_gemm_mma, cudaFuncAttributeMaxDynamicSharedMemorySize, GSM_TOT);
    }

    cudaEventRecord(evRoot, 0);

    // s2: full edge sort pipeline — starts at t=0
    cudaStreamWaitEvent(s2, evRoot, 0);
    k_count<<<NE/1024, 256, 0, s2>>>(ei);
    k_scan <<<1, 1024, 0, s2>>>();
    k_scat <<<NE/256, 256, 0, s2>>>(ei, ea);
    cudaEventRecord(evScat, s2);

    // s3: vecs+kedge (no deps, hidden under gru2) -> b16 convert
    cudaStreamWaitEvent(s3, evRoot, 0);
    k_vecs_r<<<dim3(13, 3), 256, 0, s3>>>(Wgat, att_src, att_dst, Wedge, att_edge);
    cudaEventRecord(evVecs, s3);
    k_b16   <<<(CD*KDIM + 255)/256, 256, 0, s3>>>(Wgat);
    cudaEventRecord(evB16, s3);

    // main: gru2 at t=0 (no deps!), then asrc (needs vecs), then fused agg (needs scat)
    k_gru2 <<<512, 128>>>(x, Wih, Whh, bih, bhh);
    cudaStreamWaitEvent(0, evVecs, 0);
    k_asrc <<<1024, 256>>>();
    cudaStreamWaitEvent(0, evScat, 0);
    k_agg3 <<<NNODES/2, 128>>>(0);
    cudaEventRecord(evAgg0, 0);
    k_agg3 <<<NNODES/2, 128>>>(NNODES/2);

    // s3: gemm lower half overlapped with agg upper half
    cudaStreamWaitEvent(s3, evAgg0, 0);
    k_gemm_mma<<<dim3(2, 32), 384, GSM_TOT, s3>>>(gat_bias, Wp1, 0);
    cudaEventRecord(evGemm0, s3);

    // main: gemm upper half (needs b16)
    cudaStreamWaitEvent(0, evB16, 0);
    k_gemm_mma<<<dim3(2, 32), 384, GSM_TOT>>>(gat_bias, Wp1, 32);
    cudaStreamWaitEvent(0, evGemm0, 0);
    cudaEventRecord(evGemmAll, 0);

    // s2: cls after full gemm (pooled filled by gemm epilogue)
    cudaStreamWaitEvent(s2, evGemmAll, 0);
    k_cls  <<<1, 256, 0, s2>>>(Wc1, bc1, Wc2, bc2, out, out_size);
    cudaEventRecord(evCls, s2);

    // main: pred stage 2 (tiny), then join cls
    k_pred2<<<NNODES/256, 256>>>(bp1, Wp3, bp3, out);
    cudaStreamWaitEvent(0, evCls, 0);
}